// round 6
// baseline (speedup 1.0000x reference)
#include <cuda_runtime.h>
#include <cuda_bf16.h>
#include <cstdint>

namespace {
using u64 = unsigned long long;

__device__ __forceinline__ u64 pk(float x) {
  u64 d; unsigned xi = __float_as_uint(x);
  asm("mov.b64 %0, {%1, %1};" : "=l"(d) : "r"(xi));
  return d;
}
__device__ __forceinline__ u64 ffma2(u64 a, u64 b, u64 c) {
  u64 d;
  asm("fma.rn.f32x2 %0, %1, %2, %3;" : "=l"(d) : "l"(a), "l"(b), "l"(c));
  return d;
}
__device__ __forceinline__ float2 unpk(u64 d) {
  unsigned lo, hi;
  asm("mov.b64 {%0, %1}, %2;" : "=r"(lo), "=r"(hi) : "l"(d));
  return make_float2(__uint_as_float(lo), __uint_as_float(hi));
}

struct P {
  const float *feat0, *feat1, *edge_inv;
  const int *src, *dst;
  const float *b00, *b01, *b10, *b11;
  const float *w1[4], *bb1[4], *w2[4], *bb2[4], *w3[4];  // 00,01,10,11
  float* out;
  int E;
};

__device__ __forceinline__ void cpcopy(float* d, const float* __restrict__ s, int n) {
  for (int i = threadIdx.x; i < n; i += blockDim.x) d[i] = s[i];
}
__device__ __forceinline__ void stage_mlp(float* dst, const P& p, int pr) {
  cpcopy(dst, p.w1[pr], 64);
  cpcopy(dst + 64, p.bb1[pr], 32);
  cpcopy(dst + 96, p.w2[pr], 1024);
  cpcopy(dst + 1120, p.bb2[pr], 32);
}

// h2 = relu(relu(ei@w1+b1)@w2+b2). mlp smem: w1[64]|b1[32]|w2[1024]|b2[32]
__device__ __forceinline__ void radial(const float* __restrict__ mlp,
                                       float ei0, float ei1, float h2[32]) {
  const float* w1 = mlp; const float* b1 = mlp + 64;
  const float* w2 = mlp + 96; const float* b2 = mlp + 1120;
  float h1[32];
#pragma unroll
  for (int m = 0; m < 32; m++)
    h1[m] = fmaxf(fmaf(ei0, w1[m], fmaf(ei1, w1[32 + m], b1[m])), 0.f);
  u64 a[16];
#pragma unroll
  for (int j = 0; j < 8; j++) {
    ulonglong2 b = *reinterpret_cast<const ulonglong2*>(b2 + j*4);
    a[j*2] = b.x; a[j*2+1] = b.y;
  }
#pragma unroll
  for (int n = 0; n < 32; n++) {
    u64 h = pk(h1[n]);
    const float* wr = w2 + n*32;
#pragma unroll
    for (int j = 0; j < 8; j++) {
      ulonglong2 w = *reinterpret_cast<const ulonglong2*>(wr + j*4);
      a[j*2]   = ffma2(h, w.x, a[j*2]);
      a[j*2+1] = ffma2(h, w.y, a[j*2+1]);
    }
  }
#pragma unroll
  for (int j = 0; j < 16; j++) {
    float2 q = unpk(a[j]);
    h2[j*2]   = fmaxf(q.x, 0.f);
    h2[j*2+1] = fmaxf(q.y, 0.f);
  }
}

// Contract h2 vs nf=1 w3 block [m*256 + c*16 + k], dot vec[16], add into o[16].
__device__ __forceinline__ void contract16(const float* __restrict__ w3,
                                           const float h2[32], const float vec[16],
                                           float o[16]) {
#pragma unroll 1
  for (int c = 0; c < 16; c++) {
    u64 A[8];
#pragma unroll
    for (int j = 0; j < 8; j++) A[j] = 0ull;
#pragma unroll
    for (int m = 0; m < 32; m++) {
      u64 h = pk(h2[m]);
      const float* wr = w3 + c*16 + m*256;
#pragma unroll
      for (int kb = 0; kb < 4; kb++) {
        ulonglong2 w = *reinterpret_cast<const ulonglong2*>(wr + kb*4);
        A[kb*2]   = ffma2(h, w.x, A[kb*2]);
        A[kb*2+1] = ffma2(h, w.y, A[kb*2+1]);
      }
    }
    float v = 0.f;
#pragma unroll
    for (int kb = 0; kb < 4; kb++) {
      float2 x = unpk(A[kb*2]);
      float2 y = unpk(A[kb*2+1]);
      v += x.x*vec[kb*4] + x.y*vec[kb*4+1] + y.x*vec[kb*4+2] + y.y*vec[kb*4+3];
    }
    o[c] += v;
  }
}

__global__ void zero_out(float* o, int n) {
  int i = blockIdx.x * blockDim.x + threadIdx.x;
  if (i < n) o[i] = 0.f;
}

// ---------- convA: pairs (0,0)+(1,0) -> out[..,c,0] ----------
// smem: w3_00[8192] | w3_10[8192] | mlp00[1152] | mlp10[1152]
constexpr int A_W00 = 0, A_W10 = 8192, A_M00 = 16384, A_M10 = 17536;
constexpr int A_FLOATS = 18688;   // 74752 B  (x3 CTA = 224 KB)

__global__ void __launch_bounds__(256, 3) convA(P p) {
  extern __shared__ float sm[];
  cpcopy(sm + A_W00, p.w3[0], 8192);
  cpcopy(sm + A_W10, p.w3[2], 8192);
  stage_mlp(sm + A_M00, p, 0);
  stage_mlp(sm + A_M10, p, 2);
  __syncthreads();

  int e = blockIdx.x * 256 + threadIdx.x;
  if (e >= p.E) return;
  int s = p.src[e], d = p.dst[e];
  float ei0 = p.edge_inv[2*e], ei1 = p.edge_inv[2*e+1];

  float o0[16];
#pragma unroll
  for (int c = 0; c < 16; c++) o0[c] = 0.f;

  {  // pair (0,0), b00 folded into h2
    float h2[32];
    radial(sm + A_M00, ei0, ei1, h2);
    float bv = p.b00[e];
#pragma unroll
    for (int m = 0; m < 32; m++) h2[m] *= bv;
    float f0[16];
    const float4* f0p = reinterpret_cast<const float4*>(p.feat0 + (size_t)s*16);
#pragma unroll
    for (int q = 0; q < 4; q++) {
      float4 x = f0p[q];
      f0[q*4] = x.x; f0[q*4+1] = x.y; f0[q*4+2] = x.z; f0[q*4+3] = x.w;
    }
    contract16(sm + A_W00, h2, f0, o0);
  }
  {  // pair (1,0): t1[k] = sum_i feat1[s,k,i]*b10[e,i]
    float h2[32];
    radial(sm + A_M10, ei0, ei1, h2);
    float g0 = p.b10[e*3], g1 = p.b10[e*3+1], g2 = p.b10[e*3+2];
    const float4* f1p = reinterpret_cast<const float4*>(p.feat1 + (size_t)s*48);
    float t1[16];
#pragma unroll
    for (int kb = 0; kb < 4; kb++) {
      float4 x0 = f1p[kb*3], x1 = f1p[kb*3+1], x2 = f1p[kb*3+2];
      t1[kb*4]   = x0.x*g0 + x0.y*g1 + x0.z*g2;
      t1[kb*4+1] = x0.w*g0 + x1.x*g1 + x1.y*g2;
      t1[kb*4+2] = x1.z*g0 + x1.w*g1 + x2.x*g2;
      t1[kb*4+3] = x2.y*g0 + x2.z*g1 + x2.w*g2;
    }
    contract16(sm + A_W10, h2, t1, o0);
  }

  float* outp = p.out + (size_t)d*64;
#pragma unroll 1
  for (int c = 0; c < 16; c++) atomicAdd(outp + c*4, o0[c]);
}

// ---------- conv01: pair (0,1) -> out[..,c,1..3] ----------
// smem: w3_01[8192] | mlp01[1152]
constexpr int C1_W = 0, C1_M = 8192;
constexpr int C1_FLOATS = 9344;   // 37376 B  (x3 CTA = 112 KB)

__global__ void __launch_bounds__(256, 3) conv01(P p) {
  extern __shared__ float sm[];
  cpcopy(sm + C1_W, p.w3[1], 8192);
  stage_mlp(sm + C1_M, p, 1);
  __syncthreads();

  int e = blockIdx.x * 256 + threadIdx.x;
  if (e >= p.E) return;
  int s = p.src[e], d = p.dst[e];
  float ei0 = p.edge_inv[2*e], ei1 = p.edge_inv[2*e+1];

  float h2[32];
  radial(sm + C1_M, ei0, ei1, h2);
  float f0[16];
  const float4* f0p = reinterpret_cast<const float4*>(p.feat0 + (size_t)s*16);
#pragma unroll
  for (int q = 0; q < 4; q++) {
    float4 x = f0p[q];
    f0[q*4] = x.x; f0[q*4+1] = x.y; f0[q*4+2] = x.z; f0[q*4+3] = x.w;
  }
  float v01[16];
#pragma unroll
  for (int c = 0; c < 16; c++) v01[c] = 0.f;
  contract16(sm + C1_W, h2, f0, v01);

  float q0 = p.b01[e*3], q1 = p.b01[e*3+1], q2 = p.b01[e*3+2];
  float* outp = p.out + (size_t)d*64;
#pragma unroll 1
  for (int c = 0; c < 16; c++) {
    atomicAdd(outp + c*4 + 1, v01[c]*q0);
    atomicAdd(outp + c*4 + 2, v01[c]*q1);
    atomicAdd(outp + c*4 + 3, v01[c]*q2);
  }
}

// ---------- conv11: pair (1,1) -> out[..,c,1..3], 2 threads/edge (c-halves) ----------
// smem: w3_11[24576] | mlp11[1152]
constexpr int C2_W = 0, C2_M = 24576;
constexpr int C2_FLOATS = 25728;  // 102912 B  (x2 CTA = 206 KB)

__global__ void __launch_bounds__(256, 2) conv11(P p) {
  extern __shared__ float sm[];
  cpcopy(sm + C2_W, p.w3[3], 24576);
  stage_mlp(sm + C2_M, p, 3);
  __syncthreads();

  int t = threadIdx.x;
  int e = blockIdx.x * 128 + (t >> 1);
  if (e >= p.E) return;
  int c0 = (t & 1) * 8;               // this thread's 8 output channels
  int s = p.src[e], d = p.dst[e];
  float ei0 = p.edge_inv[2*e], ei1 = p.edge_inv[2*e+1];

  float h2[32];
  radial(sm + C2_M, ei0, ei1, h2);

  float B27[27];
#pragma unroll
  for (int i = 0; i < 27; i++) B27[i] = p.b11[(size_t)e*27 + i];

  float o1[24];
#pragma unroll
  for (int j = 0; j < 24; j++) o1[j] = 0.f;

  const float* f1b = p.feat1 + (size_t)s*48;
  const float* w3d = sm + C2_W;

#pragma unroll 1
  for (int cinb = 0; cinb < 4; cinb++) {
    const float4* f1p = reinterpret_cast<const float4*>(f1b + cinb*12);
    float4 x0 = f1p[0], x1 = f1p[1], x2 = f1p[2];
    float f1v[12] = {x0.x,x0.y,x0.z,x0.w, x1.x,x1.y,x1.z,x1.w, x2.x,x2.y,x2.z,x2.w};

#pragma unroll 1
    for (int cl = 0; cl < 8; cl++) {
      int c = c0 + cl;
      u64 acc[6];
#pragma unroll
      for (int j = 0; j < 6; j++) acc[j] = 0ull;
      const float* w = w3d + c*48 + cinb*12;
#pragma unroll
      for (int m = 0; m < 32; m++) {
        u64 h = pk(h2[m]);
        const float* wr = w + m*768;
        ulonglong2 W0 = *reinterpret_cast<const ulonglong2*>(wr);
        ulonglong2 W1 = *reinterpret_cast<const ulonglong2*>(wr + 4);
        ulonglong2 W2 = *reinterpret_cast<const ulonglong2*>(wr + 8);
        acc[0] = ffma2(h, W0.x, acc[0]); acc[1] = ffma2(h, W0.y, acc[1]);
        acc[2] = ffma2(h, W1.x, acc[2]); acc[3] = ffma2(h, W1.y, acc[3]);
        acc[4] = ffma2(h, W2.x, acc[4]); acc[5] = ffma2(h, W2.y, acc[5]);
      }
      float a[12];
#pragma unroll
      for (int j = 0; j < 6; j++) {
        float2 pr = unpk(acc[j]);
        a[j*2] = pr.x; a[j*2+1] = pr.y;
      }
      // a[cc*3+f] = rw11[c, cinb*4+cc, f]
      // o1[cl][o] += sum_{cc,i} f1v[cc*3+i] * (sum_f a[cc*3+f]*B27[i*9+f*3+o])
      float r0 = o1[cl*3], r1 = o1[cl*3+1], r2 = o1[cl*3+2];
#pragma unroll
      for (int cc = 0; cc < 4; cc++) {
        float av0 = a[cc*3], av1 = a[cc*3+1], av2 = a[cc*3+2];
#pragma unroll
        for (int i = 0; i < 3; i++) {
          const float* Bi = B27 + i*9;
          float u0 = av0*Bi[0] + av1*Bi[3] + av2*Bi[6];
          float u1 = av0*Bi[1] + av1*Bi[4] + av2*Bi[7];
          float u2 = av0*Bi[2] + av1*Bi[5] + av2*Bi[8];
          float fv = f1v[cc*3+i];
          r0 = fmaf(fv, u0, r0);
          r1 = fmaf(fv, u1, r1);
          r2 = fmaf(fv, u2, r2);
        }
      }
      o1[cl*3] = r0; o1[cl*3+1] = r1; o1[cl*3+2] = r2;
    }
  }

  float* outp = p.out + (size_t)d*64;
#pragma unroll 1
  for (int cl = 0; cl < 8; cl++) {
    int c = c0 + cl;
    atomicAdd(outp + c*4 + 1, o1[cl*3]);
    atomicAdd(outp + c*4 + 2, o1[cl*3+1]);
    atomicAdd(outp + c*4 + 3, o1[cl*3+2]);
  }
}

// ---------- scalar tail (E % 256 edges; weights from gmem) ----------
__device__ void radial_g(const float* w1, const float* b1, const float* w2,
                         const float* b2, float ei0, float ei1, float h2[32]) {
  float h1[32];
  for (int m = 0; m < 32; m++)
    h1[m] = fmaxf(fmaf(ei0, w1[m], fmaf(ei1, w1[32+m], b1[m])), 0.f);
  for (int m = 0; m < 32; m++) {
    float a = b2[m];
    for (int n = 0; n < 32; n++) a = fmaf(h1[n], w2[n*32 + m], a);
    h2[m] = fmaxf(a, 0.f);
  }
}

__global__ void convTail(P p, int e0) {
  int e = e0 + threadIdx.x;
  if (e >= p.E) return;
  int s = p.src[e], d = p.dst[e];
  float ei0 = p.edge_inv[2*e], ei1 = p.edge_inv[2*e+1];
  float f0[16], f1[48];
  for (int i = 0; i < 16; i++) f0[i] = p.feat0[(size_t)s*16 + i];
  for (int i = 0; i < 48; i++) f1[i] = p.feat1[(size_t)s*48 + i];
  float h2[32], out0[16], o1[48];
  for (int c = 0; c < 16; c++) out0[c] = 0.f;
  for (int j = 0; j < 48; j++) o1[j] = 0.f;
  // pair00
  radial_g(p.w1[0], p.bb1[0], p.w2[0], p.bb2[0], ei0, ei1, h2);
  float bv = p.b00[e];
  for (int c = 0; c < 16; c++) {
    float v = 0.f;
    for (int k = 0; k < 16; k++) {
      float rw = 0.f;
      for (int m = 0; m < 32; m++) rw = fmaf(h2[m], p.w3[0][m*256 + c*16 + k], rw);
      v = fmaf(rw, f0[k], v);
    }
    out0[c] += v * bv;
  }
  // pair01
  radial_g(p.w1[1], p.bb1[1], p.w2[1], p.bb2[1], ei0, ei1, h2);
  float q0 = p.b01[e*3], q1 = p.b01[e*3+1], q2 = p.b01[e*3+2];
  for (int c = 0; c < 16; c++) {
    float v = 0.f;
    for (int k = 0; k < 16; k++) {
      float rw = 0.f;
      for (int m = 0; m < 32; m++) rw = fmaf(h2[m], p.w3[1][m*256 + c*16 + k], rw);
      v = fmaf(rw, f0[k], v);
    }
    o1[c*3] += v*q0; o1[c*3+1] += v*q1; o1[c*3+2] += v*q2;
  }
  // pair10
  radial_g(p.w1[2], p.bb1[2], p.w2[2], p.bb2[2], ei0, ei1, h2);
  float g0 = p.b10[e*3], g1 = p.b10[e*3+1], g2 = p.b10[e*3+2];
  for (int c = 0; c < 16; c++) {
    float v = 0.f;
    for (int k = 0; k < 16; k++) {
      float rw = 0.f;
      for (int m = 0; m < 32; m++) rw = fmaf(h2[m], p.w3[2][m*256 + c*16 + k], rw);
      v = fmaf(rw, f1[k*3]*g0 + f1[k*3+1]*g1 + f1[k*3+2]*g2, v);
    }
    out0[c] += v;
  }
  // pair11
  radial_g(p.w1[3], p.bb1[3], p.w2[3], p.bb2[3], ei0, ei1, h2);
  for (int c = 0; c < 16; c++) {
    for (int k = 0; k < 16; k++) {
      for (int f = 0; f < 3; f++) {
        float rw = 0.f;
        for (int m = 0; m < 32; m++) rw = fmaf(h2[m], p.w3[3][m*768 + c*48 + k*3 + f], rw);
        for (int o = 0; o < 3; o++) {
          float t = f1[k*3]*p.b11[(size_t)e*27 + f*3 + o]
                  + f1[k*3+1]*p.b11[(size_t)e*27 + 9 + f*3 + o]
                  + f1[k*3+2]*p.b11[(size_t)e*27 + 18 + f*3 + o];
          o1[c*3+o] = fmaf(rw, t, o1[c*3+o]);
        }
      }
    }
  }
  float* outp = p.out + (size_t)d * 64;
  for (int c = 0; c < 16; c++) {
    atomicAdd(outp + c*4,     out0[c]);
    atomicAdd(outp + c*4 + 1, o1[c*3]);
    atomicAdd(outp + c*4 + 2, o1[c*3+1]);
    atomicAdd(outp + c*4 + 3, o1[c*3+2]);
  }
}

}  // namespace

extern "C" void kernel_launch(void* const* d_in, const int* in_sizes, int n_in,
                              void* d_out, int out_size) {
  P p{};
  p.feat0    = (const float*)d_in[0];
  p.feat1    = (const float*)d_in[1];
  p.edge_inv = (const float*)d_in[2];
  p.src      = (const int*)d_in[3];
  p.dst      = (const int*)d_in[4];
  p.b00 = (const float*)d_in[5];
  p.b01 = (const float*)d_in[6];
  p.b10 = (const float*)d_in[7];
  p.b11 = (const float*)d_in[8];
  const int base[4] = {9, 14, 19, 24};   // 00, 01, 10, 11
  for (int pr = 0; pr < 4; pr++) {
    p.w1[pr]  = (const float*)d_in[base[pr]];
    p.bb1[pr] = (const float*)d_in[base[pr]+1];
    p.w2[pr]  = (const float*)d_in[base[pr]+2];
    p.bb2[pr] = (const float*)d_in[base[pr]+3];
    p.w3[pr]  = (const float*)d_in[base[pr]+4];
  }
  p.out = (float*)d_out;
  p.E = in_sizes[3];

  static bool attr_done = false;
  if (!attr_done) {
    cudaFuncSetAttribute(convA,  cudaFuncAttributeMaxDynamicSharedMemorySize, A_FLOATS*4);
    cudaFuncSetAttribute(conv01, cudaFuncAttributeMaxDynamicSharedMemorySize, C1_FLOATS*4);
    cudaFuncSetAttribute(conv11, cudaFuncAttributeMaxDynamicSharedMemorySize, C2_FLOATS*4);
    attr_done = true;
  }

  zero_out<<<(out_size + 511)/512, 512>>>(p.out, out_size);

  int Emain = p.E & ~255;
  if (Emain > 0) {
    int grid256 = Emain / 256;
    convA <<<grid256,     256, A_FLOATS*4>>>(p);
    conv01<<<grid256,     256, C1_FLOATS*4>>>(p);
    conv11<<<Emain / 128, 256, C2_FLOATS*4>>>(p);
  }
  int tail = p.E - Emain;
  if (tail > 0) convTail<<<1, tail>>>(p, Emain);
}

// round 8
// speedup vs baseline: 1.8499x; 1.8499x over previous
#include <cuda_runtime.h>
#include <cstdint>

namespace {
using u64 = unsigned long long;

__device__ __forceinline__ u64 pk(float x) {
  u64 d; unsigned xi = __float_as_uint(x);
  asm("mov.b64 %0, {%1, %1};" : "=l"(d) : "r"(xi));
  return d;
}
__device__ __forceinline__ u64 ffma2(u64 a, u64 b, u64 c) {
  u64 d;
  asm("fma.rn.f32x2 %0, %1, %2, %3;" : "=l"(d) : "l"(a), "l"(b), "l"(c));
  return d;
}
__device__ __forceinline__ float2 unpk(u64 d) {
  unsigned lo, hi;
  asm("mov.b64 {%0, %1}, %2;" : "=r"(lo), "=r"(hi) : "l"(d));
  return make_float2(__uint_as_float(lo), __uint_as_float(hi));
}

struct P {
  const float *feat0, *feat1, *edge_inv;
  const int *src, *dst;
  const float *b00, *b01, *b10, *b11;
  const float *w1[4], *bb1[4], *w2[4], *bb2[4], *w3[4];  // 00,01,10,11
  float* out;
  int E;
};

// pair11 W3 reordered f-major: [f][m][c*16+k]
__device__ float g_W3T11[24576];

__global__ void prep11(const float* __restrict__ w3) {
  int i = blockIdx.x * 256 + threadIdx.x;
  if (i >= 24576) return;
  int f = i >> 13;
  int r = i & 8191;
  int m = r >> 8;
  int n = r & 255;
  int c = n >> 4, k = n & 15;
  g_W3T11[i] = w3[m*768 + c*48 + k*3 + f];
}

__global__ void zero_out(float* o, int n) {
  int i = blockIdx.x * blockDim.x + threadIdx.x;
  if (i < n) o[i] = 0.f;
}

// smem float offsets
constexpr int S_F0  = 0;        // [128][16]
constexpr int S_F1  = 2048;     // [128][48]
constexpr int S_EB  = 8192;     // [128][10]: ei0,ei1,b00,b01x3,b10x3,dst(int)
constexpr int S_B11 = 9472;     // [128][27]
constexpr int S_H2T = 12928;    // [32][128]
constexpr int S_W3  = 17024;    // [32][256]
constexpr int S_MLP = 25216;    // 1152
constexpr int S_TOT = 26368;    // 105472 bytes

// h2 half (16 outputs) of radial MLP; weights in smem.
__device__ __forceinline__ void radial_half(const float* __restrict__ mlp,
                                            float ei0, float ei1, int mhalf,
                                            float h2[16]) {
  const float* w1 = mlp; const float* b1 = mlp + 64;
  const float* w2 = mlp + 96; const float* b2 = mlp + 1120;
  float h1[32];
#pragma unroll
  for (int j = 0; j < 32; j++)
    h1[j] = fmaxf(fmaf(ei0, w1[j], fmaf(ei1, w1[32 + j], b1[j])), 0.f);
  u64 acc[8];
  const u64* b2p = reinterpret_cast<const u64*>(b2 + mhalf);
#pragma unroll
  for (int j = 0; j < 8; j++) acc[j] = b2p[j];
#pragma unroll
  for (int n = 0; n < 32; n++) {
    u64 h = pk(h1[n]);
    const u64* wrow = reinterpret_cast<const u64*>(w2 + n*32 + mhalf);
#pragma unroll
    for (int j = 0; j < 8; j++) acc[j] = ffma2(h, wrow[j], acc[j]);
  }
#pragma unroll
  for (int j = 0; j < 8; j++) {
    float2 q = unpk(acc[j]);
    h2[2*j]   = fmaxf(q.x, 0.f);
    h2[2*j+1] = fmaxf(q.y, 0.f);
  }
}

// 8 edges x 8 cols register-tiled GEMM over m=32.
// H = H2T + ehalf*64 + er*8 (row stride 128); W = W3S + cr*8 (row stride 256).
__device__ __forceinline__ void gemm8x8(const float* __restrict__ H,
                                        const float* __restrict__ W,
                                        u64 acc[8][4]) {
#pragma unroll
  for (int i = 0; i < 8; i++)
#pragma unroll
    for (int j = 0; j < 4; j++) acc[i][j] = 0ull;
#pragma unroll 8
  for (int m = 0; m < 32; m++) {
    float4 a0 = *reinterpret_cast<const float4*>(H + m*128);
    float4 a1 = *reinterpret_cast<const float4*>(H + m*128 + 4);
    ulonglong2 bA = *reinterpret_cast<const ulonglong2*>(W + m*256);
    ulonglong2 bB = *reinterpret_cast<const ulonglong2*>(W + m*256 + 4);
    u64 b0 = bA.x, b1 = bA.y, b2 = bB.x, b3 = bB.y;
    u64 a;
    a = pk(a0.x); acc[0][0]=ffma2(a,b0,acc[0][0]); acc[0][1]=ffma2(a,b1,acc[0][1]); acc[0][2]=ffma2(a,b2,acc[0][2]); acc[0][3]=ffma2(a,b3,acc[0][3]);
    a = pk(a0.y); acc[1][0]=ffma2(a,b0,acc[1][0]); acc[1][1]=ffma2(a,b1,acc[1][1]); acc[1][2]=ffma2(a,b2,acc[1][2]); acc[1][3]=ffma2(a,b3,acc[1][3]);
    a = pk(a0.z); acc[2][0]=ffma2(a,b0,acc[2][0]); acc[2][1]=ffma2(a,b1,acc[2][1]); acc[2][2]=ffma2(a,b2,acc[2][2]); acc[2][3]=ffma2(a,b3,acc[2][3]);
    a = pk(a0.w); acc[3][0]=ffma2(a,b0,acc[3][0]); acc[3][1]=ffma2(a,b1,acc[3][1]); acc[3][2]=ffma2(a,b2,acc[3][2]); acc[3][3]=ffma2(a,b3,acc[3][3]);
    a = pk(a1.x); acc[4][0]=ffma2(a,b0,acc[4][0]); acc[4][1]=ffma2(a,b1,acc[4][1]); acc[4][2]=ffma2(a,b2,acc[4][2]); acc[4][3]=ffma2(a,b3,acc[4][3]);
    a = pk(a1.y); acc[5][0]=ffma2(a,b0,acc[5][0]); acc[5][1]=ffma2(a,b1,acc[5][1]); acc[5][2]=ffma2(a,b2,acc[5][2]); acc[5][3]=ffma2(a,b3,acc[5][3]);
    a = pk(a1.z); acc[6][0]=ffma2(a,b0,acc[6][0]); acc[6][1]=ffma2(a,b1,acc[6][1]); acc[6][2]=ffma2(a,b2,acc[6][2]); acc[6][3]=ffma2(a,b3,acc[6][3]);
    a = pk(a1.w); acc[7][0]=ffma2(a,b0,acc[7][0]); acc[7][1]=ffma2(a,b1,acc[7][1]); acc[7][2]=ffma2(a,b2,acc[7][2]); acc[7][3]=ffma2(a,b3,acc[7][3]);
  }
}

__device__ __forceinline__ void unpack8(const u64 a[4], float r[8]) {
  float2 q0 = unpk(a[0]), q1 = unpk(a[1]), q2 = unpk(a[2]), q3 = unpk(a[3]);
  r[0]=q0.x; r[1]=q0.y; r[2]=q1.x; r[3]=q1.y; r[4]=q2.x; r[5]=q2.y; r[6]=q3.x; r[7]=q3.y;
}

__global__ void __launch_bounds__(256, 2) convFused(P p) {
  extern __shared__ float sm[];
  int t = threadIdx.x;
  int eb = blockIdx.x * 128;

  // ---------- stage per-edge data ----------
  if (t < 128) {
    int e = eb + t;
    float* EB = sm + S_EB + t*10;
    if (e < p.E) {
      EB[0] = p.edge_inv[2*e];
      EB[1] = p.edge_inv[2*e+1];
      EB[2] = p.b00[e];
      EB[3] = p.b01[3*e]; EB[4] = p.b01[3*e+1]; EB[5] = p.b01[3*e+2];
      EB[6] = p.b10[3*e]; EB[7] = p.b10[3*e+1]; EB[8] = p.b10[3*e+2];
      reinterpret_cast<int*>(EB)[9] = p.dst[e];
    }
  }
  {
    int el = t >> 1;
    int e = eb + el;
    int half = t & 1;
    if (e < p.E) {
      int s = p.src[e];
      const float4* f0g = reinterpret_cast<const float4*>(p.feat0 + (size_t)s*16);
      float4* f0s = reinterpret_cast<float4*>(sm + S_F0 + el*16);
      f0s[half*2+0] = f0g[half*2+0];
      f0s[half*2+1] = f0g[half*2+1];
      const float4* f1g = reinterpret_cast<const float4*>(p.feat1 + (size_t)s*48);
      float4* f1s = reinterpret_cast<float4*>(sm + S_F1 + el*48);
#pragma unroll
      for (int q = 0; q < 6; q++) f1s[half*6+q] = f1g[half*6+q];
      const float* bg = p.b11 + (size_t)e*27;
      float* bs = sm + S_B11 + el*27;
      for (int q = half; q < 27; q += 2) bs[q] = bg[q];
    }
  }

  int er = t >> 5, cr = t & 31;
  int c = cr >> 1, khalf = (cr & 1) * 8;
  int el2 = t >> 1, mhalf = (t & 1) * 16;

  auto stage_mlp = [&](int pr) {
    float* d = sm + S_MLP;
    if (t < 64) d[t] = p.w1[pr][t];
    else if (t < 96) d[64 + (t-64)] = p.bb1[pr][t-64];
    else if (t < 128) d[1120 + (t-96)] = p.bb2[pr][t-96];
    for (int i = t; i < 1024; i += 256) d[96 + i] = p.w2[pr][i];
  };

  auto do_radial = [&](int pr, bool fold_b00) {
    int e = eb + el2;
    if (e < p.E) {
      const float* EB = sm + S_EB + el2*10;
      float h2[16];
      radial_half(sm + S_MLP, EB[0], EB[1], mhalf, h2);
      float sc = fold_b00 ? EB[2] : 1.f;
#pragma unroll
      for (int j = 0; j < 16; j++)
        sm[S_H2T + (mhalf + j)*128 + el2] = h2[j] * sc;
    } else {
#pragma unroll
      for (int j = 0; j < 16; j++)
        sm[S_H2T + (mhalf + j)*128 + el2] = 0.f;
    }
  };

  auto stage_w3_g = [&](const float* __restrict__ g) {
    float4* d = reinterpret_cast<float4*>(sm + S_W3);
    const float4* s4 = reinterpret_cast<const float4*>(g);
#pragma unroll
    for (int q = 0; q < 8; q++) d[t + 256*q] = s4[t + 256*q];
  };

  // ================= pair 00 (b00 folded) -> out[..,c,0] =================
  stage_mlp(0);
  __syncthreads();
  do_radial(0, true);
  stage_w3_g(p.w3[0]);
  __syncthreads();
#pragma unroll 1
  for (int eh = 0; eh < 2; eh++) {
    u64 acc[8][4];
    gemm8x8(sm + S_H2T + eh*64 + er*8, sm + S_W3 + cr*8, acc);
#pragma unroll
    for (int i = 0; i < 8; i++) {
      int el = eh*64 + er*8 + i;
      int e = eb + el;
      if (e < p.E) {
        float rw[8]; unpack8(acc[i], rw);
        const float* f0 = sm + S_F0 + el*16 + khalf;
        float v = 0.f;
#pragma unroll
        for (int j = 0; j < 8; j++) v = fmaf(rw[j], f0[j], v);
        v += __shfl_xor_sync(0xffffffffu, v, 1);
        if ((cr & 1) == 0) {
          int dd = reinterpret_cast<const int*>(sm + S_EB + el*10)[9];
          atomicAdd(p.out + (size_t)dd*64 + c*4, v);
        }
      }
    }
  }

  // ================= pair 01 -> out[..,c,1..3] =================
  __syncthreads();
  stage_mlp(1);
  __syncthreads();
  do_radial(1, false);
  stage_w3_g(p.w3[1]);
  __syncthreads();
#pragma unroll 1
  for (int eh = 0; eh < 2; eh++) {
    u64 acc[8][4];
    gemm8x8(sm + S_H2T + eh*64 + er*8, sm + S_W3 + cr*8, acc);
#pragma unroll
    for (int i = 0; i < 8; i++) {
      int el = eh*64 + er*8 + i;
      int e = eb + el;
      if (e < p.E) {
        float rw[8]; unpack8(acc[i], rw);
        const float* f0 = sm + S_F0 + el*16 + khalf;
        float v = 0.f;
#pragma unroll
        for (int j = 0; j < 8; j++) v = fmaf(rw[j], f0[j], v);
        v += __shfl_xor_sync(0xffffffffu, v, 1);
        if ((cr & 1) == 0) {
          const float* EB = sm + S_EB + el*10;
          int dd = reinterpret_cast<const int*>(EB)[9];
          float* outp = p.out + (size_t)dd*64 + c*4;
          atomicAdd(outp + 1, v * EB[3]);
          atomicAdd(outp + 2, v * EB[4]);
          atomicAdd(outp + 3, v * EB[5]);
        }
      }
    }
  }

  // ================= pair 10 -> out[..,c,0] =================
  __syncthreads();
  stage_mlp(2);
  __syncthreads();
  do_radial(2, false);
  stage_w3_g(p.w3[2]);
  __syncthreads();
#pragma unroll 1
  for (int eh = 0; eh < 2; eh++) {
    u64 acc[8][4];
    gemm8x8(sm + S_H2T + eh*64 + er*8, sm + S_W3 + cr*8, acc);
#pragma unroll
    for (int i = 0; i < 8; i++) {
      int el = eh*64 + er*8 + i;
      int e = eb + el;
      if (e < p.E) {
        float rw[8]; unpack8(acc[i], rw);
        const float* EB = sm + S_EB + el*10;
        float g0 = EB[6], g1 = EB[7], g2 = EB[8];
        const float* f1 = sm + S_F1 + el*48 + khalf*3;
        float v = 0.f;
#pragma unroll
        for (int j = 0; j < 8; j++) {
          float t1 = f1[j*3]*g0 + f1[j*3+1]*g1 + f1[j*3+2]*g2;
          v = fmaf(rw[j], t1, v);
        }
        v += __shfl_xor_sync(0xffffffffu, v, 1);
        if ((cr & 1) == 0) {
          int dd = reinterpret_cast<const int*>(EB)[9];
          atomicAdd(p.out + (size_t)dd*64 + c*4, v);
        }
      }
    }
  }

  // ================= pair 11 -> out[..,c,1..3] =================
  __syncthreads();
  stage_mlp(3);
  __syncthreads();
  do_radial(3, false);
  __syncthreads();
#pragma unroll 1
  for (int f = 0; f < 3; f++) {
    stage_w3_g(g_W3T11 + f*8192);
    __syncthreads();
#pragma unroll 1
    for (int eh = 0; eh < 2; eh++) {
      u64 acc[8][4];
      gemm8x8(sm + S_H2T + eh*64 + er*8, sm + S_W3 + cr*8, acc);
#pragma unroll
      for (int i = 0; i < 8; i++) {
        int el = eh*64 + er*8 + i;
        int e = eb + el;
        if (e < p.E) {
          float rw[8]; unpack8(acc[i], rw);
          const float* f1 = sm + S_F1 + el*48 + khalf*3;
          float s0 = 0.f, s1 = 0.f, s2 = 0.f;
#pragma unroll
          for (int j = 0; j < 8; j++) {
            float r = rw[j];
            s0 = fmaf(r, f1[j*3],   s0);
            s1 = fmaf(r, f1[j*3+1], s1);
            s2 = fmaf(r, f1[j*3+2], s2);
          }
          const float* B = sm + S_B11 + el*27 + f*3;   // B[i*9 + f*3 + o]
          float p0 = s0*B[0] + s1*B[9]  + s2*B[18];
          float p1 = s0*B[1] + s1*B[10] + s2*B[19];
          float p2 = s0*B[2] + s1*B[11] + s2*B[20];
          p0 += __shfl_xor_sync(0xffffffffu, p0, 1);
          p1 += __shfl_xor_sync(0xffffffffu, p1, 1);
          p2 += __shfl_xor_sync(0xffffffffu, p2, 1);
          if ((cr & 1) == 0) {
            int dd = reinterpret_cast<const int*>(sm + S_EB + el*10)[9];
            float* outp = p.out + (size_t)dd*64 + c*4;
            atomicAdd(outp + 1, p0);
            atomicAdd(outp + 2, p1);
            atomicAdd(outp + 3, p2);
          }
        }
      }
    }
    __syncthreads();
  }
}

}  // namespace

extern "C" void kernel_launch(void* const* d_in, const int* in_sizes, int n_in,
                              void* d_out, int out_size) {
  P p{};
  p.feat0    = (const float*)d_in[0];
  p.feat1    = (const float*)d_in[1];
  p.edge_inv = (const float*)d_in[2];
  p.src      = (const int*)d_in[3];
  p.dst      = (const int*)d_in[4];
  p.b00 = (const float*)d_in[5];
  p.b01 = (const float*)d_in[6];
  p.b10 = (const float*)d_in[7];
  p.b11 = (const float*)d_in[8];
  const int base[4] = {9, 14, 19, 24};   // 00, 01, 10, 11
  for (int pr = 0; pr < 4; pr++) {
    p.w1[pr]  = (const float*)d_in[base[pr]];
    p.bb1[pr] = (const float*)d_in[base[pr]+1];
    p.w2[pr]  = (const float*)d_in[base[pr]+2];
    p.bb2[pr] = (const float*)d_in[base[pr]+3];
    p.w3[pr]  = (const float*)d_in[base[pr]+4];
  }
  p.out = (float*)d_out;
  p.E = in_sizes[3];

  static bool attr_done = false;
  if (!attr_done) {
    cudaFuncSetAttribute(convFused, cudaFuncAttributeMaxDynamicSharedMemorySize,
                         S_TOT * 4);
    attr_done = true;
  }

  prep11<<<96, 256>>>(p.w3[3]);
  zero_out<<<(out_size + 511)/512, 512>>>(p.out, out_size);
  int grid = (p.E + 127) / 128;
  convFused<<<grid, 256, S_TOT * 4>>>(p);
}

// round 9
// speedup vs baseline: 1.8958x; 1.0248x over previous
#include <cuda_runtime.h>
#include <cstdint>

namespace {
using u64 = unsigned long long;

__device__ __forceinline__ u64 pk(float x) {
  u64 d; unsigned xi = __float_as_uint(x);
  asm("mov.b64 %0, {%1, %1};" : "=l"(d) : "r"(xi));
  return d;
}
__device__ __forceinline__ u64 ffma2(u64 a, u64 b, u64 c) {
  u64 d;
  asm("fma.rn.f32x2 %0, %1, %2, %3;" : "=l"(d) : "l"(a), "l"(b), "l"(c));
  return d;
}
__device__ __forceinline__ float2 unpk(u64 d) {
  unsigned lo, hi;
  asm("mov.b64 {%0, %1}, %2;" : "=r"(lo), "=r"(hi) : "l"(d));
  return make_float2(__uint_as_float(lo), __uint_as_float(hi));
}

struct P {
  const float *feat0, *feat1, *edge_inv;
  const int *src, *dst;
  const float *b00, *b01, *b10, *b11;
  const float *w1[4], *bb1[4], *w2[4], *bb2[4], *w3[4];  // 00,01,10,11
  float* out;
  int E;
};

// pair11 W3 reordered f-major: [f][m][c*16+k]
__device__ float g_W3T11[24576];

__global__ void prolog(const float* __restrict__ w3_11, float* out, int nout) {
  int i = blockIdx.x * 256 + threadIdx.x;
  if (i < nout) out[i] = 0.f;
  if (i < 24576) {
    int f = i >> 13;
    int r = i & 8191;
    int m = r >> 8;
    int n = r & 255;
    int c = n >> 4, k = n & 15;
    g_W3T11[i] = w3_11[m*768 + c*48 + k*3 + f];
  }
}

// smem float offsets
constexpr int S_F0  = 0;        // [128][16]  f0; reused as t1 after pair01
constexpr int S_F1  = 2048;     // [128][48]
constexpr int S_EB  = 8192;     // [128][10]: ei0,ei1,b00,b01x3,b10x3,dst(int)
constexpr int S_B11 = 9472;     // [128][27]
constexpr int S_H2T = 12928;    // [32][128]
constexpr int S_W3  = 17024;    // [32][256]
constexpr int S_MLPA= 25216;    // 1152
constexpr int S_MLPB= 26368;    // 1152
constexpr int S_TOT = 27520;    // 110080 bytes (x2 CTA = 220 KB)

// h2 half (16 outputs) of radial MLP; weights in smem.
__device__ __forceinline__ void radial_half(const float* __restrict__ mlp,
                                            float ei0, float ei1, int mhalf,
                                            float h2[16]) {
  const float* w1 = mlp; const float* b1 = mlp + 64;
  const float* w2 = mlp + 96; const float* b2 = mlp + 1120;
  float h1[32];
#pragma unroll
  for (int j = 0; j < 32; j++)
    h1[j] = fmaxf(fmaf(ei0, w1[j], fmaf(ei1, w1[32 + j], b1[j])), 0.f);
  u64 acc[8];
  const u64* b2p = reinterpret_cast<const u64*>(b2 + mhalf);
#pragma unroll
  for (int j = 0; j < 8; j++) acc[j] = b2p[j];
#pragma unroll
  for (int n = 0; n < 32; n++) {
    u64 h = pk(h1[n]);
    const u64* wrow = reinterpret_cast<const u64*>(w2 + n*32 + mhalf);
#pragma unroll
    for (int j = 0; j < 8; j++) acc[j] = ffma2(h, wrow[j], acc[j]);
  }
#pragma unroll
  for (int j = 0; j < 8; j++) {
    float2 q = unpk(acc[j]);
    h2[2*j]   = fmaxf(q.x, 0.f);
    h2[2*j+1] = fmaxf(q.y, 0.f);
  }
}

// 8 edges x 8 cols register-tiled GEMM over m=32.
__device__ __forceinline__ void gemm8x8(const float* __restrict__ H,
                                        const float* __restrict__ W,
                                        u64 acc[8][4]) {
#pragma unroll
  for (int i = 0; i < 8; i++)
#pragma unroll
    for (int j = 0; j < 4; j++) acc[i][j] = 0ull;
#pragma unroll 8
  for (int m = 0; m < 32; m++) {
    float4 a0 = *reinterpret_cast<const float4*>(H + m*128);
    float4 a1 = *reinterpret_cast<const float4*>(H + m*128 + 4);
    ulonglong2 bA = *reinterpret_cast<const ulonglong2*>(W + m*256);
    ulonglong2 bB = *reinterpret_cast<const ulonglong2*>(W + m*256 + 4);
    u64 b0 = bA.x, b1 = bA.y, b2 = bB.x, b3 = bB.y;
    u64 a;
    a = pk(a0.x); acc[0][0]=ffma2(a,b0,acc[0][0]); acc[0][1]=ffma2(a,b1,acc[0][1]); acc[0][2]=ffma2(a,b2,acc[0][2]); acc[0][3]=ffma2(a,b3,acc[0][3]);
    a = pk(a0.y); acc[1][0]=ffma2(a,b0,acc[1][0]); acc[1][1]=ffma2(a,b1,acc[1][1]); acc[1][2]=ffma2(a,b2,acc[1][2]); acc[1][3]=ffma2(a,b3,acc[1][3]);
    a = pk(a0.z); acc[2][0]=ffma2(a,b0,acc[2][0]); acc[2][1]=ffma2(a,b1,acc[2][1]); acc[2][2]=ffma2(a,b2,acc[2][2]); acc[2][3]=ffma2(a,b3,acc[2][3]);
    a = pk(a0.w); acc[3][0]=ffma2(a,b0,acc[3][0]); acc[3][1]=ffma2(a,b1,acc[3][1]); acc[3][2]=ffma2(a,b2,acc[3][2]); acc[3][3]=ffma2(a,b3,acc[3][3]);
    a = pk(a1.x); acc[4][0]=ffma2(a,b0,acc[4][0]); acc[4][1]=ffma2(a,b1,acc[4][1]); acc[4][2]=ffma2(a,b2,acc[4][2]); acc[4][3]=ffma2(a,b3,acc[4][3]);
    a = pk(a1.y); acc[5][0]=ffma2(a,b0,acc[5][0]); acc[5][1]=ffma2(a,b1,acc[5][1]); acc[5][2]=ffma2(a,b2,acc[5][2]); acc[5][3]=ffma2(a,b3,acc[5][3]);
    a = pk(a1.z); acc[6][0]=ffma2(a,b0,acc[6][0]); acc[6][1]=ffma2(a,b1,acc[6][1]); acc[6][2]=ffma2(a,b2,acc[6][2]); acc[6][3]=ffma2(a,b3,acc[6][3]);
    a = pk(a1.w); acc[7][0]=ffma2(a,b0,acc[7][0]); acc[7][1]=ffma2(a,b1,acc[7][1]); acc[7][2]=ffma2(a,b2,acc[7][2]); acc[7][3]=ffma2(a,b3,acc[7][3]);
  }
}

__device__ __forceinline__ void unpack8(const u64 a[4], float r[8]) {
  float2 q0 = unpk(a[0]), q1 = unpk(a[1]), q2 = unpk(a[2]), q3 = unpk(a[3]);
  r[0]=q0.x; r[1]=q0.y; r[2]=q1.x; r[3]=q1.y; r[4]=q2.x; r[5]=q2.y; r[6]=q3.x; r[7]=q3.y;
}

// Guard-free main kernel: every block covers 128 valid edges.
__global__ void __launch_bounds__(256, 2) convFused(P p) {
  extern __shared__ float sm[];
  int t = threadIdx.x;
  int eb = blockIdx.x * 128;
  int er = t >> 5, cr = t & 31;
  int c = cr >> 1, khalf = (cr & 1) * 8;
  int el2 = t >> 1, mhalf = (t & 1) * 16;

  // ---------- stage per-edge data ----------
  if (t < 128) {
    int e = eb + t;
    float* EB = sm + S_EB + t*10;
    EB[0] = p.edge_inv[2*e];
    EB[1] = p.edge_inv[2*e+1];
    EB[2] = p.b00[e];
    EB[3] = p.b01[3*e]; EB[4] = p.b01[3*e+1]; EB[5] = p.b01[3*e+2];
    EB[6] = p.b10[3*e]; EB[7] = p.b10[3*e+1]; EB[8] = p.b10[3*e+2];
    reinterpret_cast<int*>(EB)[9] = p.dst[e];
  }
  {
    int half = t & 1;
    int e = eb + el2;
    int s = p.src[e];
    const float4* f0g = reinterpret_cast<const float4*>(p.feat0 + (size_t)s*16);
    float4* f0s = reinterpret_cast<float4*>(sm + S_F0 + el2*16);
    f0s[half*2+0] = f0g[half*2+0];
    f0s[half*2+1] = f0g[half*2+1];
    const float4* f1g = reinterpret_cast<const float4*>(p.feat1 + (size_t)s*48);
    float4* f1s = reinterpret_cast<float4*>(sm + S_F1 + el2*48);
#pragma unroll
    for (int q = 0; q < 6; q++) f1s[half*6+q] = f1g[half*6+q];
    const float* bg = p.b11 + (size_t)e*27;
    float* bs = sm + S_B11 + el2*27;
    for (int q = half; q < 27; q += 2) bs[q] = bg[q];
  }

  auto stage_mlp = [&](int pr, int off) {
    float* d = sm + off;
    if (t < 64) d[t] = p.w1[pr][t];
    else if (t < 96) d[64 + (t-64)] = p.bb1[pr][t-64];
    else if (t < 128) d[1120 + (t-96)] = p.bb2[pr][t-96];
    for (int i = t; i < 1024; i += 256) d[96 + i] = p.w2[pr][i];
  };
  auto do_radial = [&](int off, bool fold) {
    const float* EB = sm + S_EB + el2*10;
    float h2[16];
    radial_half(sm + off, EB[0], EB[1], mhalf, h2);
    float sc = fold ? EB[2] : 1.f;
#pragma unroll
    for (int j = 0; j < 16; j++)
      sm[S_H2T + (mhalf + j)*128 + el2] = h2[j] * sc;
  };
  auto w3load = [&](const float* __restrict__ g, float4 r[8]) {
    const float4* s4 = reinterpret_cast<const float4*>(g);
#pragma unroll
    for (int q = 0; q < 8; q++) r[q] = s4[t + 256*q];
  };
  auto w3store = [&](const float4 r[8]) {
    float4* d = reinterpret_cast<float4*>(sm + S_W3);
#pragma unroll
    for (int q = 0; q < 8; q++) d[t + 256*q] = r[q];
  };

  float4 wreg[8];

  stage_mlp(0, S_MLPA);
  __syncthreads();

  // ---- chunk 0: pair00 (b00 folded) -> out[..,c,0] ----
  w3load(p.w3[0], wreg);
  do_radial(S_MLPA, true);
  w3store(wreg);
  __syncthreads();
#pragma unroll 1
  for (int eh = 0; eh < 2; eh++) {
    u64 acc[8][4];
    gemm8x8(sm + S_H2T + eh*64 + er*8, sm + S_W3 + cr*8, acc);
#pragma unroll
    for (int i = 0; i < 8; i++) {
      int el = eh*64 + er*8 + i;
      const u64* f0p = reinterpret_cast<const u64*>(sm + S_F0 + el*16 + khalf);
      u64 v2 = ffma2(acc[i][0], f0p[0], 0ull);
      v2 = ffma2(acc[i][1], f0p[1], v2);
      v2 = ffma2(acc[i][2], f0p[2], v2);
      v2 = ffma2(acc[i][3], f0p[3], v2);
      float2 q = unpk(v2);
      float v = q.x + q.y;
      v += __shfl_xor_sync(0xffffffffu, v, 1);
      if ((cr & 1) == 0) {
        int dd = reinterpret_cast<const int*>(sm + S_EB + el*10)[9];
        atomicAdd(p.out + (size_t)dd*64 + c*4, v);
      }
    }
  }
  stage_mlp(1, S_MLPB);
  w3load(p.w3[1], wreg);
  __syncthreads();

  // ---- chunk 1: pair01 -> out[..,c,1..3] ----
  do_radial(S_MLPB, false);
  w3store(wreg);
  __syncthreads();
#pragma unroll 1
  for (int eh = 0; eh < 2; eh++) {
    u64 acc[8][4];
    gemm8x8(sm + S_H2T + eh*64 + er*8, sm + S_W3 + cr*8, acc);
#pragma unroll
    for (int i = 0; i < 8; i++) {
      int el = eh*64 + er*8 + i;
      const u64* f0p = reinterpret_cast<const u64*>(sm + S_F0 + el*16 + khalf);
      u64 v2 = ffma2(acc[i][0], f0p[0], 0ull);
      v2 = ffma2(acc[i][1], f0p[1], v2);
      v2 = ffma2(acc[i][2], f0p[2], v2);
      v2 = ffma2(acc[i][3], f0p[3], v2);
      float2 q = unpk(v2);
      float v = q.x + q.y;
      v += __shfl_xor_sync(0xffffffffu, v, 1);
      if ((cr & 1) == 0) {
        const float* EB = sm + S_EB + el*10;
        int dd = reinterpret_cast<const int*>(EB)[9];
        float* outp = p.out + (size_t)dd*64 + c*4;
        atomicAdd(outp + 1, v * EB[3]);
        atomicAdd(outp + 2, v * EB[4]);
        atomicAdd(outp + 3, v * EB[5]);
      }
    }
  }
  stage_mlp(2, S_MLPA);
  w3load(p.w3[2], wreg);
  __syncthreads();

  // ---- chunk 2: pair10 -> out[..,c,0]; t1 precomputed into S_F0 ----
  do_radial(S_MLPA, false);
  {
    int half = t & 1, kh = half*8;
    const float* EB = sm + S_EB + el2*10;
    float g0 = EB[6], g1 = EB[7], g2 = EB[8];
    const float* f1 = sm + S_F1 + el2*48 + kh*3;
    float* t1 = sm + S_F0 + el2*16 + kh;
#pragma unroll
    for (int j = 0; j < 8; j++)
      t1[j] = f1[j*3]*g0 + f1[j*3+1]*g1 + f1[j*3+2]*g2;
  }
  w3store(wreg);
  __syncthreads();
#pragma unroll 1
  for (int eh = 0; eh < 2; eh++) {
    u64 acc[8][4];
    gemm8x8(sm + S_H2T + eh*64 + er*8, sm + S_W3 + cr*8, acc);
#pragma unroll
    for (int i = 0; i < 8; i++) {
      int el = eh*64 + er*8 + i;
      const u64* t1p = reinterpret_cast<const u64*>(sm + S_F0 + el*16 + khalf);
      u64 v2 = ffma2(acc[i][0], t1p[0], 0ull);
      v2 = ffma2(acc[i][1], t1p[1], v2);
      v2 = ffma2(acc[i][2], t1p[2], v2);
      v2 = ffma2(acc[i][3], t1p[3], v2);
      float2 q = unpk(v2);
      float v = q.x + q.y;
      v += __shfl_xor_sync(0xffffffffu, v, 1);
      if ((cr & 1) == 0) {
        int dd = reinterpret_cast<const int*>(sm + S_EB + el*10)[9];
        atomicAdd(p.out + (size_t)dd*64 + c*4, v);
      }
    }
  }
  stage_mlp(3, S_MLPB);
  w3load(g_W3T11, wreg);
  __syncthreads();

  // ---- chunks 3..5: pair11 (f = 0,1,2) -> out[..,c,1..3] ----
  do_radial(S_MLPB, false);
  w3store(wreg);
  __syncthreads();
#pragma unroll 1
  for (int f = 0; f < 3; f++) {
#pragma unroll 1
    for (int eh = 0; eh < 2; eh++) {
      u64 acc[8][4];
      gemm8x8(sm + S_H2T + eh*64 + er*8, sm + S_W3 + cr*8, acc);
#pragma unroll
      for (int i = 0; i < 8; i++) {
        int el = eh*64 + er*8 + i;
        float rw[8]; unpack8(acc[i], rw);
        const float* f1 = sm + S_F1 + el*48 + khalf*3;
        float s0 = 0.f, s1 = 0.f, s2 = 0.f;
#pragma unroll
        for (int j = 0; j < 8; j++) {
          float r = rw[j];
          s0 = fmaf(r, f1[j*3],   s0);
          s1 = fmaf(r, f1[j*3+1], s1);
          s2 = fmaf(r, f1[j*3+2], s2);
        }
        const float* B = sm + S_B11 + el*27 + f*3;   // B[i*9 + f*3 + o]
        float p0 = s0*B[0] + s1*B[9]  + s2*B[18];
        float p1 = s0*B[1] + s1*B[10] + s2*B[19];
        float p2 = s0*B[2] + s1*B[11] + s2*B[20];
        p0 += __shfl_xor_sync(0xffffffffu, p0, 1);
        p1 += __shfl_xor_sync(0xffffffffu, p1, 1);
        p2 += __shfl_xor_sync(0xffffffffu, p2, 1);
        if ((cr & 1) == 0) {
          int dd = reinterpret_cast<const int*>(sm + S_EB + el*10)[9];
          float* outp = p.out + (size_t)dd*64 + c*4;
          atomicAdd(outp + 1, p0);
          atomicAdd(outp + 2, p1);
          atomicAdd(outp + 3, p2);
        }
      }
    }
    if (f < 2) {
      w3load(g_W3T11 + (f+1)*8192, wreg);
      __syncthreads();
      w3store(wreg);
      __syncthreads();
    }
  }
}

// ---------- scalar tail (E % 128 edges; weights from gmem) ----------
__device__ void radial_g(const float* w1, const float* b1, const float* w2,
                         const float* b2, float ei0, float ei1, float h2[32]) {
  float h1[32];
  for (int m = 0; m < 32; m++)
    h1[m] = fmaxf(fmaf(ei0, w1[m], fmaf(ei1, w1[32+m], b1[m])), 0.f);
  for (int m = 0; m < 32; m++) {
    float a = b2[m];
    for (int n = 0; n < 32; n++) a = fmaf(h1[n], w2[n*32 + m], a);
    h2[m] = fmaxf(a, 0.f);
  }
}

__global__ void convTail(P p, int e0) {
  int e = e0 + threadIdx.x;
  if (e >= p.E) return;
  int s = p.src[e], d = p.dst[e];
  float ei0 = p.edge_inv[2*e], ei1 = p.edge_inv[2*e+1];
  float f0[16], f1[48];
  for (int i = 0; i < 16; i++) f0[i] = p.feat0[(size_t)s*16 + i];
  for (int i = 0; i < 48; i++) f1[i] = p.feat1[(size_t)s*48 + i];
  float h2[32], out0[16], o1[48];
  for (int c = 0; c < 16; c++) out0[c] = 0.f;
  for (int j = 0; j < 48; j++) o1[j] = 0.f;
  radial_g(p.w1[0], p.bb1[0], p.w2[0], p.bb2[0], ei0, ei1, h2);
  float bv = p.b00[e];
  for (int c = 0; c < 16; c++) {
    float v = 0.f;
    for (int k = 0; k < 16; k++) {
      float rw = 0.f;
      for (int m = 0; m < 32; m++) rw = fmaf(h2[m], p.w3[0][m*256 + c*16 + k], rw);
      v = fmaf(rw, f0[k], v);
    }
    out0[c] += v * bv;
  }
  radial_g(p.w1[1], p.bb1[1], p.w2[1], p.bb2[1], ei0, ei1, h2);
  float q0 = p.b01[e*3], q1 = p.b01[e*3+1], q2 = p.b01[e*3+2];
  for (int c = 0; c < 16; c++) {
    float v = 0.f;
    for (int k = 0; k < 16; k++) {
      float rw = 0.f;
      for (int m = 0; m < 32; m++) rw = fmaf(h2[m], p.w3[1][m*256 + c*16 + k], rw);
      v = fmaf(rw, f0[k], v);
    }
    o1[c*3] += v*q0; o1[c*3+1] += v*q1; o1[c*3+2] += v*q2;
  }
  radial_g(p.w1[2], p.bb1[2], p.w2[2], p.bb2[2], ei0, ei1, h2);
  float g0 = p.b10[e*3], g1 = p.b10[e*3+1], g2 = p.b10[e*3+2];
  for (int c = 0; c < 16; c++) {
    float v = 0.f;
    for (int k = 0; k < 16; k++) {
      float rw = 0.f;
      for (int m = 0; m < 32; m++) rw = fmaf(h2[m], p.w3[2][m*256 + c*16 + k], rw);
      v = fmaf(rw, f1[k*3]*g0 + f1[k*3+1]*g1 + f1[k*3+2]*g2, v);
    }
    out0[c] += v;
  }
  radial_g(p.w1[3], p.bb1[3], p.w2[3], p.bb2[3], ei0, ei1, h2);
  for (int c = 0; c < 16; c++) {
    for (int k = 0; k < 16; k++) {
      for (int f = 0; f < 3; f++) {
        float rw = 0.f;
        for (int m = 0; m < 32; m++) rw = fmaf(h2[m], p.w3[3][m*768 + c*48 + k*3 + f], rw);
        for (int o = 0; o < 3; o++) {
          float tt = f1[k*3]*p.b11[(size_t)e*27 + f*3 + o]
                   + f1[k*3+1]*p.b11[(size_t)e*27 + 9 + f*3 + o]
                   + f1[k*3+2]*p.b11[(size_t)e*27 + 18 + f*3 + o];
          o1[c*3+o] = fmaf(rw, tt, o1[c*3+o]);
        }
      }
    }
  }
  float* outp = p.out + (size_t)d * 64;
  for (int c = 0; c < 16; c++) {
    atomicAdd(outp + c*4,     out0[c]);
    atomicAdd(outp + c*4 + 1, o1[c*3]);
    atomicAdd(outp + c*4 + 2, o1[c*3+1]);
    atomicAdd(outp + c*4 + 3, o1[c*3+2]);
  }
}

}  // namespace

extern "C" void kernel_launch(void* const* d_in, const int* in_sizes, int n_in,
                              void* d_out, int out_size) {
  P p{};
  p.feat0    = (const float*)d_in[0];
  p.feat1    = (const float*)d_in[1];
  p.edge_inv = (const float*)d_in[2];
  p.src      = (const int*)d_in[3];
  p.dst      = (const int*)d_in[4];
  p.b00 = (const float*)d_in[5];
  p.b01 = (const float*)d_in[6];
  p.b10 = (const float*)d_in[7];
  p.b11 = (const float*)d_in[8];
  const int base[4] = {9, 14, 19, 24};   // 00, 01, 10, 11
  for (int pr = 0; pr < 4; pr++) {
    p.w1[pr]  = (const float*)d_in[base[pr]];
    p.bb1[pr] = (const float*)d_in[base[pr]+1];
    p.w2[pr]  = (const float*)d_in[base[pr]+2];
    p.bb2[pr] = (const float*)d_in[base[pr]+3];
    p.w3[pr]  = (const float*)d_in[base[pr]+4];
  }
  p.out = (float*)d_out;
  p.E = in_sizes[3];

  static bool attr_done = false;
  if (!attr_done) {
    cudaFuncSetAttribute(convFused, cudaFuncAttributeMaxDynamicSharedMemorySize,
                         S_TOT * 4);
    attr_done = true;
  }

  int nblk = (out_size + 255) / 256;
  if (nblk < 96) nblk = 96;
  prolog<<<nblk, 256>>>(p.w3[3], p.out, out_size);

  int nfull = p.E / 128;
  if (nfull > 0) convFused<<<nfull, 256, S_TOT * 4>>>(p);
  int tail = p.E - nfull * 128;
  if (tail > 0) convTail<<<1, tail>>>(p, nfull * 128);
}

// round 10
// speedup vs baseline: 2.0266x; 1.0689x over previous
#include <cuda_runtime.h>
#include <cstdint>

namespace {
using u64 = unsigned long long;

__device__ __forceinline__ u64 pk(float x) {
  u64 d; unsigned xi = __float_as_uint(x);
  asm("mov.b64 %0, {%1, %1};" : "=l"(d) : "r"(xi));
  return d;
}
__device__ __forceinline__ u64 ffma2(u64 a, u64 b, u64 c) {
  u64 d;
  asm("fma.rn.f32x2 %0, %1, %2, %3;" : "=l"(d) : "l"(a), "l"(b), "l"(c));
  return d;
}
__device__ __forceinline__ float2 unpk(u64 d) {
  unsigned lo, hi;
  asm("mov.b64 {%0, %1}, %2;" : "=r"(lo), "=r"(hi) : "l"(d));
  return make_float2(__uint_as_float(lo), __uint_as_float(hi));
}

struct P {
  const float *feat0, *feat1, *edge_inv;
  const int *src, *dst;
  const float *b00, *b01, *b10, *b11;
  const float *w1[4], *bb1[4], *w2[4], *bb2[4], *w3[4];  // 00,01,10,11
  float* out;
  int E;
};

// pair11 W3 reordered f-major: [f][m][c*16+k]  (logical layout; smem permute at store)
__device__ float g_W3T11[24576];

__global__ void prolog(const float* __restrict__ w3_11, float* out, int nout) {
  int i = blockIdx.x * 256 + threadIdx.x;
  if (i < nout) out[i] = 0.f;
  if (i < 24576) {
    int f = i >> 13;
    int r = i & 8191;
    int m = r >> 8;
    int n = r & 255;
    int c = n >> 4, k = n & 15;
    g_W3T11[i] = w3_11[m*768 + c*48 + k*3 + f];
  }
}

// smem float offsets
constexpr int S_F0  = 0;        // [128][16]  f0; reused as t1 after pair01
constexpr int S_F1  = 2048;     // [128][48]
constexpr int S_EB  = 8192;     // [128][10]: ei0,ei1,b00,b01x3,b10x3,dst(int)
constexpr int S_B11 = 9472;     // [128][27]
constexpr int S_H2T = 12928;    // [32][128]
constexpr int S_W3  = 17024;    // [32][256]  (column-permuted: n=8t+j -> 4t+j | 128+4t+j-4)
constexpr int S_MLPA= 25216;    // 1152
constexpr int S_MLPB= 26368;    // 1152
constexpr int S_TOT = 27520;    // 110080 bytes (x2 CTA = 220 KB)

// h2 half (16 outputs) of radial MLP; weights in smem.
__device__ __forceinline__ void radial_half(const float* __restrict__ mlp,
                                            float ei0, float ei1, int mhalf,
                                            float h2[16]) {
  const float* w1 = mlp; const float* b1 = mlp + 64;
  const float* w2 = mlp + 96; const float* b2 = mlp + 1120;
  float h1[32];
#pragma unroll
  for (int j = 0; j < 32; j++)
    h1[j] = fmaxf(fmaf(ei0, w1[j], fmaf(ei1, w1[32 + j], b1[j])), 0.f);
  u64 acc[8];
  const u64* b2p = reinterpret_cast<const u64*>(b2 + mhalf);
#pragma unroll
  for (int j = 0; j < 8; j++) acc[j] = b2p[j];
#pragma unroll
  for (int n = 0; n < 32; n++) {
    u64 h = pk(h1[n]);
    const u64* wrow = reinterpret_cast<const u64*>(w2 + n*32 + mhalf);
#pragma unroll
    for (int j = 0; j < 8; j++) acc[j] = ffma2(h, wrow[j], acc[j]);
  }
#pragma unroll
  for (int j = 0; j < 8; j++) {
    float2 q = unpk(acc[j]);
    h2[2*j]   = fmaxf(q.x, 0.f);
    h2[2*j+1] = fmaxf(q.y, 0.f);
  }
}

// 8 edges x 8 cols register-tiled GEMM over m=32.
// W points at sm + S_W3 + cr*4; dense 16B lane stride -> conflict-free.
// Physical layout: cols [cr*8..cr*8+3] at W, cols [cr*8+4..cr*8+7] at W+128.
__device__ __forceinline__ void gemm8x8(const float* __restrict__ H,
                                        const float* __restrict__ W,
                                        u64 acc[8][4]) {
#pragma unroll
  for (int i = 0; i < 8; i++)
#pragma unroll
    for (int j = 0; j < 4; j++) acc[i][j] = 0ull;
#pragma unroll 8
  for (int m = 0; m < 32; m++) {
    float4 a0 = *reinterpret_cast<const float4*>(H + m*128);
    float4 a1 = *reinterpret_cast<const float4*>(H + m*128 + 4);
    ulonglong2 bA = *reinterpret_cast<const ulonglong2*>(W + m*256);
    ulonglong2 bB = *reinterpret_cast<const ulonglong2*>(W + m*256 + 128);
    u64 b0 = bA.x, b1 = bA.y, b2 = bB.x, b3 = bB.y;
    u64 a;
    a = pk(a0.x); acc[0][0]=ffma2(a,b0,acc[0][0]); acc[0][1]=ffma2(a,b1,acc[0][1]); acc[0][2]=ffma2(a,b2,acc[0][2]); acc[0][3]=ffma2(a,b3,acc[0][3]);
    a = pk(a0.y); acc[1][0]=ffma2(a,b0,acc[1][0]); acc[1][1]=ffma2(a,b1,acc[1][1]); acc[1][2]=ffma2(a,b2,acc[1][2]); acc[1][3]=ffma2(a,b3,acc[1][3]);
    a = pk(a0.z); acc[2][0]=ffma2(a,b0,acc[2][0]); acc[2][1]=ffma2(a,b1,acc[2][1]); acc[2][2]=ffma2(a,b2,acc[2][2]); acc[2][3]=ffma2(a,b3,acc[2][3]);
    a = pk(a0.w); acc[3][0]=ffma2(a,b0,acc[3][0]); acc[3][1]=ffma2(a,b1,acc[3][1]); acc[3][2]=ffma2(a,b2,acc[3][2]); acc[3][3]=ffma2(a,b3,acc[3][3]);
    a = pk(a1.x); acc[4][0]=ffma2(a,b0,acc[4][0]); acc[4][1]=ffma2(a,b1,acc[4][1]); acc[4][2]=ffma2(a,b2,acc[4][2]); acc[4][3]=ffma2(a,b3,acc[4][3]);
    a = pk(a1.y); acc[5][0]=ffma2(a,b0,acc[5][0]); acc[5][1]=ffma2(a,b1,acc[5][1]); acc[5][2]=ffma2(a,b2,acc[5][2]); acc[5][3]=ffma2(a,b3,acc[5][3]);
    a = pk(a1.z); acc[6][0]=ffma2(a,b0,acc[6][0]); acc[6][1]=ffma2(a,b1,acc[6][1]); acc[6][2]=ffma2(a,b2,acc[6][2]); acc[6][3]=ffma2(a,b3,acc[6][3]);
    a = pk(a1.w); acc[7][0]=ffma2(a,b0,acc[7][0]); acc[7][1]=ffma2(a,b1,acc[7][1]); acc[7][2]=ffma2(a,b2,acc[7][2]); acc[7][3]=ffma2(a,b3,acc[7][3]);
  }
}

__device__ __forceinline__ void unpack8(const u64 a[4], float r[8]) {
  float2 q0 = unpk(a[0]), q1 = unpk(a[1]), q2 = unpk(a[2]), q3 = unpk(a[3]);
  r[0]=q0.x; r[1]=q0.y; r[2]=q1.x; r[3]=q1.y; r[4]=q2.x; r[5]=q2.y; r[6]=q3.x; r[7]=q3.y;
}

// Guard-free main kernel: every block covers 128 valid edges.
__global__ void __launch_bounds__(256, 2) convFused(P p) {
  extern __shared__ float sm[];
  int t = threadIdx.x;
  int eb = blockIdx.x * 128;
  int er = t >> 5, cr = t & 31;
  int c = cr >> 1, khalf = (cr & 1) * 8;
  int el2 = t >> 1, mhalf = (t & 1) * 16;

  // ---------- stage per-edge data ----------
  if (t < 128) {
    int e = eb + t;
    float* EB = sm + S_EB + t*10;
    EB[0] = p.edge_inv[2*e];
    EB[1] = p.edge_inv[2*e+1];
    EB[2] = p.b00[e];
    EB[3] = p.b01[3*e]; EB[4] = p.b01[3*e+1]; EB[5] = p.b01[3*e+2];
    EB[6] = p.b10[3*e]; EB[7] = p.b10[3*e+1]; EB[8] = p.b10[3*e+2];
    reinterpret_cast<int*>(EB)[9] = p.dst[e];
  }
  {
    int half = t & 1;
    int e = eb + el2;
    int s = p.src[e];
    const float4* f0g = reinterpret_cast<const float4*>(p.feat0 + (size_t)s*16);
    float4* f0s = reinterpret_cast<float4*>(sm + S_F0 + el2*16);
    f0s[half*2+0] = f0g[half*2+0];
    f0s[half*2+1] = f0g[half*2+1];
    const float4* f1g = reinterpret_cast<const float4*>(p.feat1 + (size_t)s*48);
    float4* f1s = reinterpret_cast<float4*>(sm + S_F1 + el2*48);
#pragma unroll
    for (int q = 0; q < 6; q++) f1s[half*6+q] = f1g[half*6+q];
    const float* bg = p.b11 + (size_t)e*27;
    float* bs = sm + S_B11 + el2*27;
    for (int q = half; q < 27; q += 2) bs[q] = bg[q];
  }

  auto stage_mlp = [&](int pr, int off) {
    float* d = sm + off;
    if (t < 64) d[t] = p.w1[pr][t];
    else if (t < 96) d[64 + (t-64)] = p.bb1[pr][t-64];
    else if (t < 128) d[1120 + (t-96)] = p.bb2[pr][t-96];
    for (int i = t; i < 1024; i += 256) d[96 + i] = p.w2[pr][i];
  };
  auto do_radial = [&](int off, bool fold) {
    const float* EB = sm + S_EB + el2*10;
    float h2[16];
    radial_half(sm + off, EB[0], EB[1], mhalf, h2);
    float sc = fold ? EB[2] : 1.f;
#pragma unroll
    for (int j = 0; j < 16; j++)
      sm[S_H2T + (mhalf + j)*128 + el2] = h2[j] * sc;
  };
  auto w3load = [&](const float* __restrict__ g, float4 r[8]) {
    const float4* s4 = reinterpret_cast<const float4*>(g);
#pragma unroll
    for (int q = 0; q < 8; q++) r[q] = s4[t + 256*q];
  };
  // Column-permuted store: float4 index i4 covers logical cols a*4..a*4+3 of row;
  // even a -> phys f4 (a>>1); odd a -> phys f4 32+(a>>1).
  auto w3store = [&](const float4 r[8]) {
    float4* d = reinterpret_cast<float4*>(sm + S_W3);
#pragma unroll
    for (int q = 0; q < 8; q++) {
      int i4 = t + 256*q;
      int row = i4 >> 6, a = i4 & 63;
      int phys = row*64 + ((a & 1) ? 32 + (a >> 1) : (a >> 1));
      d[phys] = r[q];
    }
  };

  float4 wreg[8];

  stage_mlp(0, S_MLPA);
  __syncthreads();

  // ---- chunk 0: pair00 (b00 folded) -> out[..,c,0] ----
  w3load(p.w3[0], wreg);
  do_radial(S_MLPA, true);
  w3store(wreg);
  __syncthreads();
#pragma unroll 1
  for (int eh = 0; eh < 2; eh++) {
    u64 acc[8][4];
    gemm8x8(sm + S_H2T + eh*64 + er*8, sm + S_W3 + cr*4, acc);
#pragma unroll
    for (int i = 0; i < 8; i++) {
      int el = eh*64 + er*8 + i;
      const u64* f0p = reinterpret_cast<const u64*>(sm + S_F0 + el*16 + khalf);
      u64 v2 = ffma2(acc[i][0], f0p[0], 0ull);
      v2 = ffma2(acc[i][1], f0p[1], v2);
      v2 = ffma2(acc[i][2], f0p[2], v2);
      v2 = ffma2(acc[i][3], f0p[3], v2);
      float2 q = unpk(v2);
      float v = q.x + q.y;
      v += __shfl_xor_sync(0xffffffffu, v, 1);
      if ((cr & 1) == 0) {
        int dd = reinterpret_cast<const int*>(sm + S_EB + el*10)[9];
        atomicAdd(p.out + (size_t)dd*64 + c*4, v);
      }
    }
  }
  stage_mlp(1, S_MLPB);
  w3load(p.w3[1], wreg);
  __syncthreads();

  // ---- chunk 1: pair01 -> out[..,c,1..3] ----
  do_radial(S_MLPB, false);
  w3store(wreg);
  __syncthreads();
#pragma unroll 1
  for (int eh = 0; eh < 2; eh++) {
    u64 acc[8][4];
    gemm8x8(sm + S_H2T + eh*64 + er*8, sm + S_W3 + cr*4, acc);
#pragma unroll
    for (int i = 0; i < 8; i++) {
      int el = eh*64 + er*8 + i;
      const u64* f0p = reinterpret_cast<const u64*>(sm + S_F0 + el*16 + khalf);
      u64 v2 = ffma2(acc[i][0], f0p[0], 0ull);
      v2 = ffma2(acc[i][1], f0p[1], v2);
      v2 = ffma2(acc[i][2], f0p[2], v2);
      v2 = ffma2(acc[i][3], f0p[3], v2);
      float2 q = unpk(v2);
      float v = q.x + q.y;
      v += __shfl_xor_sync(0xffffffffu, v, 1);
      if ((cr & 1) == 0) {
        const float* EB = sm + S_EB + el*10;
        int dd = reinterpret_cast<const int*>(EB)[9];
        float* outp = p.out + (size_t)dd*64 + c*4;
        atomicAdd(outp + 1, v * EB[3]);
        atomicAdd(outp + 2, v * EB[4]);
        atomicAdd(outp + 3, v * EB[5]);
      }
    }
  }
  stage_mlp(2, S_MLPA);
  w3load(p.w3[2], wreg);
  __syncthreads();

  // ---- chunk 2: pair10 -> out[..,c,0]; t1 precomputed into S_F0 ----
  do_radial(S_MLPA, false);
  {
    int half = t & 1, kh = half*8;
    const float* EB = sm + S_EB + el2*10;
    float g0 = EB[6], g1 = EB[7], g2 = EB[8];
    const float* f1 = sm + S_F1 + el2*48 + kh*3;
    float* t1 = sm + S_F0 + el2*16 + kh;
#pragma unroll
    for (int j = 0; j < 8; j++)
      t1[j] = f1[j*3]*g0 + f1[j*3+1]*g1 + f1[j*3+2]*g2;
  }
  w3store(wreg);
  __syncthreads();
#pragma unroll 1
  for (int eh = 0; eh < 2; eh++) {
    u64 acc[8][4];
    gemm8x8(sm + S_H2T + eh*64 + er*8, sm + S_W3 + cr*4, acc);
#pragma unroll
    for (int i = 0; i < 8; i++) {
      int el = eh*64 + er*8 + i;
      const u64* t1p = reinterpret_cast<const u64*>(sm + S_F0 + el*16 + khalf);
      u64 v2 = ffma2(acc[i][0], t1p[0], 0ull);
      v2 = ffma2(acc[i][1], t1p[1], v2);
      v2 = ffma2(acc[i][2], t1p[2], v2);
      v2 = ffma2(acc[i][3], t1p[3], v2);
      float2 q = unpk(v2);
      float v = q.x + q.y;
      v += __shfl_xor_sync(0xffffffffu, v, 1);
      if ((cr & 1) == 0) {
        int dd = reinterpret_cast<const int*>(sm + S_EB + el*10)[9];
        atomicAdd(p.out + (size_t)dd*64 + c*4, v);
      }
    }
  }
  stage_mlp(3, S_MLPB);
  w3load(g_W3T11, wreg);
  __syncthreads();

  // ---- chunks 3..5: pair11 (f = 0,1,2) -> out[..,c,1..3] ----
  do_radial(S_MLPB, false);
  w3store(wreg);
  __syncthreads();
#pragma unroll 1
  for (int f = 0; f < 3; f++) {
#pragma unroll 1
    for (int eh = 0; eh < 2; eh++) {
      u64 acc[8][4];
      gemm8x8(sm + S_H2T + eh*64 + er*8, sm + S_W3 + cr*4, acc);
#pragma unroll
      for (int i = 0; i < 8; i++) {
        int el = eh*64 + er*8 + i;
        float rw[8]; unpack8(acc[i], rw);
        const float* f1 = sm + S_F1 + el*48 + khalf*3;
        float s0 = 0.f, s1 = 0.f, s2 = 0.f;
#pragma unroll
        for (int j = 0; j < 8; j++) {
          float r = rw[j];
          s0 = fmaf(r, f1[j*3],   s0);
          s1 = fmaf(r, f1[j*3+1], s1);
          s2 = fmaf(r, f1[j*3+2], s2);
        }
        const float* B = sm + S_B11 + el*27 + f*3;   // B[i*9 + f*3 + o]
        float p0 = s0*B[0] + s1*B[9]  + s2*B[18];
        float p1 = s0*B[1] + s1*B[10] + s2*B[19];
        float p2 = s0*B[2] + s1*B[11] + s2*B[20];
        p0 += __shfl_xor_sync(0xffffffffu, p0, 1);
        p1 += __shfl_xor_sync(0xffffffffu, p1, 1);
        p2 += __shfl_xor_sync(0xffffffffu, p2, 1);
        if ((cr & 1) == 0) {
          int dd = reinterpret_cast<const int*>(sm + S_EB + el*10)[9];
          float* outp = p.out + (size_t)dd*64 + c*4;
          atomicAdd(outp + 1, p0);
          atomicAdd(outp + 2, p1);
          atomicAdd(outp + 3, p2);
        }
      }
    }
    if (f < 2) {
      w3load(g_W3T11 + (f+1)*8192, wreg);
      __syncthreads();
      w3store(wreg);
      __syncthreads();
    }
  }
}

// ---------- scalar tail (E % 128 edges; weights from gmem) ----------
__device__ void radial_g(const float* w1, const float* b1, const float* w2,
                         const float* b2, float ei0, float ei1, float h2[32]) {
  float h1[32];
  for (int m = 0; m < 32; m++)
    h1[m] = fmaxf(fmaf(ei0, w1[m], fmaf(ei1, w1[32+m], b1[m])), 0.f);
  for (int m = 0; m < 32; m++) {
    float a = b2[m];
    for (int n = 0; n < 32; n++) a = fmaf(h1[n], w2[n*32 + m], a);
    h2[m] = fmaxf(a, 0.f);
  }
}

__global__ void convTail(P p, int e0) {
  int e = e0 + threadIdx.x;
  if (e >= p.E) return;
  int s = p.src[e], d = p.dst[e];
  float ei0 = p.edge_inv[2*e], ei1 = p.edge_inv[2*e+1];
  float f0[16], f1[48];
  for (int i = 0; i < 16; i++) f0[i] = p.feat0[(size_t)s*16 + i];
  for (int i = 0; i < 48; i++) f1[i] = p.feat1[(size_t)s*48 + i];
  float h2[32], out0[16], o1[48];
  for (int c = 0; c < 16; c++) out0[c] = 0.f;
  for (int j = 0; j < 48; j++) o1[j] = 0.f;
  radial_g(p.w1[0], p.bb1[0], p.w2[0], p.bb2[0], ei0, ei1, h2);
  float bv = p.b00[e];
  for (int c = 0; c < 16; c++) {
    float v = 0.f;
    for (int k = 0; k < 16; k++) {
      float rw = 0.f;
      for (int m = 0; m < 32; m++) rw = fmaf(h2[m], p.w3[0][m*256 + c*16 + k], rw);
      v = fmaf(rw, f0[k], v);
    }
    out0[c] += v * bv;
  }
  radial_g(p.w1[1], p.bb1[1], p.w2[1], p.bb2[1], ei0, ei1, h2);
  float q0 = p.b01[e*3], q1 = p.b01[e*3+1], q2 = p.b01[e*3+2];
  for (int c = 0; c < 16; c++) {
    float v = 0.f;
    for (int k = 0; k < 16; k++) {
      float rw = 0.f;
      for (int m = 0; m < 32; m++) rw = fmaf(h2[m], p.w3[1][m*256 + c*16 + k], rw);
      v = fmaf(rw, f0[k], v);
    }
    o1[c*3] += v*q0; o1[c*3+1] += v*q1; o1[c*3+2] += v*q2;
  }
  radial_g(p.w1[2], p.bb1[2], p.w2[2], p.bb2[2], ei0, ei1, h2);
  float g0 = p.b10[e*3], g1 = p.b10[e*3+1], g2 = p.b10[e*3+2];
  for (int c = 0; c < 16; c++) {
    float v = 0.f;
    for (int k = 0; k < 16; k++) {
      float rw = 0.f;
      for (int m = 0; m < 32; m++) rw = fmaf(h2[m], p.w3[2][m*256 + c*16 + k], rw);
      v = fmaf(rw, f1[k*3]*g0 + f1[k*3+1]*g1 + f1[k*3+2]*g2, v);
    }
    out0[c] += v;
  }
  radial_g(p.w1[3], p.bb1[3], p.w2[3], p.bb2[3], ei0, ei1, h2);
  for (int c = 0; c < 16; c++) {
    for (int k = 0; k < 16; k++) {
      for (int f = 0; f < 3; f++) {
        float rw = 0.f;
        for (int m = 0; m < 32; m++) rw = fmaf(h2[m], p.w3[3][m*768 + c*48 + k*3 + f], rw);
        for (int o = 0; o < 3; o++) {
          float tt = f1[k*3]*p.b11[(size_t)e*27 + f*3 + o]
                   + f1[k*3+1]*p.b11[(size_t)e*27 + 9 + f*3 + o]
                   + f1[k*3+2]*p.b11[(size_t)e*27 + 18 + f*3 + o];
          o1[c*3+o] = fmaf(rw, tt, o1[c*3+o]);
        }
      }
    }
  }
  float* outp = p.out + (size_t)d * 64;
  for (int c = 0; c < 16; c++) {
    atomicAdd(outp + c*4,     out0[c]);
    atomicAdd(outp + c*4 + 1, o1[c*3]);
    atomicAdd(outp + c*4 + 2, o1[c*3+1]);
    atomicAdd(outp + c*4 + 3, o1[c*3+2]);
  }
}

}  // namespace

extern "C" void kernel_launch(void* const* d_in, const int* in_sizes, int n_in,
                              void* d_out, int out_size) {
  P p{};
  p.feat0    = (const float*)d_in[0];
  p.feat1    = (const float*)d_in[1];
  p.edge_inv = (const float*)d_in[2];
  p.src      = (const int*)d_in[3];
  p.dst      = (const int*)d_in[4];
  p.b00 = (const float*)d_in[5];
  p.b01 = (const float*)d_in[6];
  p.b10 = (const float*)d_in[7];
  p.b11 = (const float*)d_in[8];
  const int base[4] = {9, 14, 19, 24};   // 00, 01, 10, 11
  for (int pr = 0; pr < 4; pr++) {
    p.w1[pr]  = (const float*)d_in[base[pr]];
    p.bb1[pr] = (const float*)d_in[base[pr]+1];
    p.w2[pr]  = (const float*)d_in[base[pr]+2];
    p.bb2[pr] = (const float*)d_in[base[pr]+3];
    p.w3[pr]  = (const float*)d_in[base[pr]+4];
  }
  p.out = (float*)d_out;
  p.E = in_sizes[3];

  static bool attr_done = false;
  if (!attr_done) {
    cudaFuncSetAttribute(convFused, cudaFuncAttributeMaxDynamicSharedMemorySize,
                         S_TOT * 4);
    attr_done = true;
  }

  int nblk = (out_size + 255) / 256;
  if (nblk < 96) nblk = 96;
  prolog<<<nblk, 256>>>(p.w3[3], p.out, out_size);

  int nfull = p.E / 128;
  if (nfull > 0) convFused<<<nfull, 256, S_TOT * 4>>>(p);
  int tail = p.E - nfull * 128;
  if (tail > 0) convTail<<<1, tail>>>(p, nfull * 128);
}

// round 11
// speedup vs baseline: 2.0431x; 1.0082x over previous
#include <cuda_runtime.h>
#include <cstdint>

namespace {
using u64 = unsigned long long;

__device__ __forceinline__ u64 pk(float x) {
  u64 d; unsigned xi = __float_as_uint(x);
  asm("mov.b64 %0, {%1, %1};" : "=l"(d) : "r"(xi));
  return d;
}
__device__ __forceinline__ u64 ffma2(u64 a, u64 b, u64 c) {
  u64 d;
  asm("fma.rn.f32x2 %0, %1, %2, %3;" : "=l"(d) : "l"(a), "l"(b), "l"(c));
  return d;
}
__device__ __forceinline__ float2 unpk(u64 d) {
  unsigned lo, hi;
  asm("mov.b64 {%0, %1}, %2;" : "=r"(lo), "=r"(hi) : "l"(d));
  return make_float2(__uint_as_float(lo), __uint_as_float(hi));
}

struct P {
  const float *feat0, *feat1, *edge_inv;
  const int *src, *dst;
  const float *b00, *b01, *b10, *b11;
  const float *w1[4], *bb1[4], *w2[4], *bb2[4], *w3[4];  // 00,01,10,11
  float* out;
  int E;
};

// pair11 W3 reordered f-major: [f][m][c*16+k]  (logical layout; smem permute at store)
__device__ float g_W3T11[24576];

__global__ void prolog(const float* __restrict__ w3_11, float* out, int nout) {
  int i = blockIdx.x * 256 + threadIdx.x;
  if (i < nout) out[i] = 0.f;
  if (i < 24576) {
    int f = i >> 13;
    int r = i & 8191;
    int m = r >> 8;
    int n = r & 255;
    int c = n >> 4, k = n & 15;
    g_W3T11[i] = w3_11[m*768 + c*48 + k*3 + f];
  }
}

// smem float offsets
constexpr int S_F0  = 0;        // [128][16]  f0; reused as t1 after pair01
constexpr int S_F1  = 2048;     // [128][48]
constexpr int S_EB  = 8192;     // [128][10]: ei0,ei1,b00,b01x3,b10x3,dst(int)
constexpr int S_B11 = 9472;     // [128][27]
constexpr int S_H2T = 12928;    // [32][128]
constexpr int S_W3  = 17024;    // [32][256]  (column-permuted)
constexpr int S_MLPA= 25216;    // 1152
constexpr int S_MLPB= 26368;    // 1152
constexpr int S_TOT = 27520;    // 110080 bytes (x2 CTA = 220 KB)

__device__ __forceinline__ void radial_half(const float* __restrict__ mlp,
                                            float ei0, float ei1, int mhalf,
                                            float h2[16]) {
  const float* w1 = mlp; const float* b1 = mlp + 64;
  const float* w2 = mlp + 96; const float* b2 = mlp + 1120;
  float h1[32];
#pragma unroll
  for (int j = 0; j < 32; j++)
    h1[j] = fmaxf(fmaf(ei0, w1[j], fmaf(ei1, w1[32 + j], b1[j])), 0.f);
  u64 acc[8];
  const u64* b2p = reinterpret_cast<const u64*>(b2 + mhalf);
#pragma unroll
  for (int j = 0; j < 8; j++) acc[j] = b2p[j];
#pragma unroll
  for (int n = 0; n < 32; n++) {
    u64 h = pk(h1[n]);
    const u64* wrow = reinterpret_cast<const u64*>(w2 + n*32 + mhalf);
#pragma unroll
    for (int j = 0; j < 8; j++) acc[j] = ffma2(h, wrow[j], acc[j]);
  }
#pragma unroll
  for (int j = 0; j < 8; j++) {
    float2 q = unpk(acc[j]);
    h2[2*j]   = fmaxf(q.x, 0.f);
    h2[2*j+1] = fmaxf(q.y, 0.f);
  }
}

// 8 edges x 8 cols register-tiled GEMM over m=32; conflict-free permuted B.
__device__ __forceinline__ void gemm8x8(const float* __restrict__ H,
                                        const float* __restrict__ W,
                                        u64 acc[8][4]) {
#pragma unroll
  for (int i = 0; i < 8; i++)
#pragma unroll
    for (int j = 0; j < 4; j++) acc[i][j] = 0ull;
#pragma unroll 8
  for (int m = 0; m < 32; m++) {
    float4 a0 = *reinterpret_cast<const float4*>(H + m*128);
    float4 a1 = *reinterpret_cast<const float4*>(H + m*128 + 4);
    ulonglong2 bA = *reinterpret_cast<const ulonglong2*>(W + m*256);
    ulonglong2 bB = *reinterpret_cast<const ulonglong2*>(W + m*256 + 128);
    u64 b0 = bA.x, b1 = bA.y, b2 = bB.x, b3 = bB.y;
    u64 a;
    a = pk(a0.x); acc[0][0]=ffma2(a,b0,acc[0][0]); acc[0][1]=ffma2(a,b1,acc[0][1]); acc[0][2]=ffma2(a,b2,acc[0][2]); acc[0][3]=ffma2(a,b3,acc[0][3]);
    a = pk(a0.y); acc[1][0]=ffma2(a,b0,acc[1][0]); acc[1][1]=ffma2(a,b1,acc[1][1]); acc[1][2]=ffma2(a,b2,acc[1][2]); acc[1][3]=ffma2(a,b3,acc[1][3]);
    a = pk(a0.z); acc[2][0]=ffma2(a,b0,acc[2][0]); acc[2][1]=ffma2(a,b1,acc[2][1]); acc[2][2]=ffma2(a,b2,acc[2][2]); acc[2][3]=ffma2(a,b3,acc[2][3]);
    a = pk(a0.w); acc[3][0]=ffma2(a,b0,acc[3][0]); acc[3][1]=ffma2(a,b1,acc[3][1]); acc[3][2]=ffma2(a,b2,acc[3][2]); acc[3][3]=ffma2(a,b3,acc[3][3]);
    a = pk(a1.x); acc[4][0]=ffma2(a,b0,acc[4][0]); acc[4][1]=ffma2(a,b1,acc[4][1]); acc[4][2]=ffma2(a,b2,acc[4][2]); acc[4][3]=ffma2(a,b3,acc[4][3]);
    a = pk(a1.y); acc[5][0]=ffma2(a,b0,acc[5][0]); acc[5][1]=ffma2(a,b1,acc[5][1]); acc[5][2]=ffma2(a,b2,acc[5][2]); acc[5][3]=ffma2(a,b3,acc[5][3]);
    a = pk(a1.z); acc[6][0]=ffma2(a,b0,acc[6][0]); acc[6][1]=ffma2(a,b1,acc[6][1]); acc[6][2]=ffma2(a,b2,acc[6][2]); acc[6][3]=ffma2(a,b3,acc[6][3]);
    a = pk(a1.w); acc[7][0]=ffma2(a,b0,acc[7][0]); acc[7][1]=ffma2(a,b1,acc[7][1]); acc[7][2]=ffma2(a,b2,acc[7][2]); acc[7][3]=ffma2(a,b3,acc[7][3]);
  }
}

__device__ __forceinline__ void unpack8(const u64 a[4], float r[8]) {
  float2 q0 = unpk(a[0]), q1 = unpk(a[1]), q2 = unpk(a[2]), q3 = unpk(a[3]);
  r[0]=q0.x; r[1]=q0.y; r[2]=q1.x; r[3]=q1.y; r[4]=q2.x; r[5]=q2.y; r[6]=q3.x; r[7]=q3.y;
}

// Guard-free main kernel: every block covers 128 valid edges.
__global__ void __launch_bounds__(256, 2) convFused(P p) {
  extern __shared__ float sm[];
  int t = threadIdx.x;
  int eb = blockIdx.x * 128;
  int er = t >> 5, cr = t & 31;
  int c = cr >> 1, khalf = (cr & 1) * 8;
  int el2 = t >> 1, mhalf = (t & 1) * 16;

  // ---------- stage per-edge data ----------
  if (t < 128) {
    int e = eb + t;
    float* EB = sm + S_EB + t*10;
    EB[0] = p.edge_inv[2*e];
    EB[1] = p.edge_inv[2*e+1];
    EB[2] = p.b00[e];
    EB[3] = p.b01[3*e]; EB[4] = p.b01[3*e+1]; EB[5] = p.b01[3*e+2];
    EB[6] = p.b10[3*e]; EB[7] = p.b10[3*e+1]; EB[8] = p.b10[3*e+2];
    reinterpret_cast<int*>(EB)[9] = p.dst[e];
  }
  {
    int half = t & 1;
    int e = eb + el2;
    int s = p.src[e];
    const float4* f0g = reinterpret_cast<const float4*>(p.feat0 + (size_t)s*16);
    float4* f0s = reinterpret_cast<float4*>(sm + S_F0 + el2*16);
    f0s[half*2+0] = f0g[half*2+0];
    f0s[half*2+1] = f0g[half*2+1];
    const float4* f1g = reinterpret_cast<const float4*>(p.feat1 + (size_t)s*48);
    float4* f1s = reinterpret_cast<float4*>(sm + S_F1 + el2*48);
#pragma unroll
    for (int q = 0; q < 6; q++) f1s[half*6+q] = f1g[half*6+q];
    const float* bg = p.b11 + (size_t)e*27;
    float* bs = sm + S_B11 + el2*27;
    for (int q = half; q < 27; q += 2) bs[q] = bg[q];
  }

  auto stage_mlp = [&](int pr, int off) {
    float* d = sm + off;
    if (t < 64) d[t] = p.w1[pr][t];
    else if (t < 96) d[64 + (t-64)] = p.bb1[pr][t-64];
    else if (t < 128) d[1120 + (t-96)] = p.bb2[pr][t-96];
    for (int i = t; i < 1024; i += 256) d[96 + i] = p.w2[pr][i];
  };
  auto do_radial = [&](int off, bool fold) {
    const float* EB = sm + S_EB + el2*10;
    float h2[16];
    radial_half(sm + off, EB[0], EB[1], mhalf, h2);
    float sc = fold ? EB[2] : 1.f;
#pragma unroll
    for (int j = 0; j < 16; j++)
      sm[S_H2T + (mhalf + j)*128 + el2] = h2[j] * sc;
  };
  auto w3load = [&](const float* __restrict__ g, float4 r[8]) {
    const float4* s4 = reinterpret_cast<const float4*>(g);
#pragma unroll
    for (int q = 0; q < 8; q++) r[q] = s4[t + 256*q];
  };
  auto w3store = [&](const float4 r[8]) {
    float4* d = reinterpret_cast<float4*>(sm + S_W3);
#pragma unroll
    for (int q = 0; q < 8; q++) {
      int i4 = t + 256*q;
      int row = i4 >> 6, a = i4 & 63;
      int phys = row*64 + ((a & 1) ? 32 + (a >> 1) : (a >> 1));
      d[phys] = r[q];
    }
  };

  float4 wreg[8];
  // degree-1 output accumulator (per-thread k-half partials; shfl at flush)
  float o1[16][3];

  stage_mlp(0, S_MLPA);
  __syncthreads();

  // ---- chunk 0: pair00 (b00 folded) -> out[..,c,0] ----
  w3load(p.w3[0], wreg);
  do_radial(S_MLPA, true);
  w3store(wreg);
  __syncthreads();
#pragma unroll 1
  for (int eh = 0; eh < 2; eh++) {
    u64 acc[8][4];
    gemm8x8(sm + S_H2T + eh*64 + er*8, sm + S_W3 + cr*4, acc);
#pragma unroll
    for (int i = 0; i < 8; i++) {
      int el = eh*64 + er*8 + i;
      const u64* f0p = reinterpret_cast<const u64*>(sm + S_F0 + el*16 + khalf);
      u64 v2 = ffma2(acc[i][0], f0p[0], 0ull);
      v2 = ffma2(acc[i][1], f0p[1], v2);
      v2 = ffma2(acc[i][2], f0p[2], v2);
      v2 = ffma2(acc[i][3], f0p[3], v2);
      float2 q = unpk(v2);
      float v = q.x + q.y;
      v += __shfl_xor_sync(0xffffffffu, v, 1);
      if ((cr & 1) == 0) {
        int dd = reinterpret_cast<const int*>(sm + S_EB + el*10)[9];
        atomicAdd(p.out + (size_t)dd*64 + c*4, v);
      }
    }
  }
  stage_mlp(1, S_MLPB);
  w3load(p.w3[1], wreg);
  __syncthreads();

  // ---- chunk 1: pair01 -> o1 regs (no atomics) ----
  do_radial(S_MLPB, false);
  w3store(wreg);
  __syncthreads();
#pragma unroll 1
  for (int eh = 0; eh < 2; eh++) {
    u64 acc[8][4];
    gemm8x8(sm + S_H2T + eh*64 + er*8, sm + S_W3 + cr*4, acc);
#pragma unroll
    for (int i = 0; i < 8; i++) {
      int el = eh*64 + er*8 + i;
      int idx = eh*8 + i;
      const u64* f0p = reinterpret_cast<const u64*>(sm + S_F0 + el*16 + khalf);
      u64 v2 = ffma2(acc[i][0], f0p[0], 0ull);
      v2 = ffma2(acc[i][1], f0p[1], v2);
      v2 = ffma2(acc[i][2], f0p[2], v2);
      v2 = ffma2(acc[i][3], f0p[3], v2);
      float2 q = unpk(v2);
      float v = q.x + q.y;                 // this lane's k-half partial
      const float* EB = sm + S_EB + el*10;
      o1[idx][0] = v * EB[3];
      o1[idx][1] = v * EB[4];
      o1[idx][2] = v * EB[5];
    }
  }
  stage_mlp(2, S_MLPA);
  w3load(p.w3[2], wreg);
  __syncthreads();

  // ---- chunk 2: pair10 -> out[..,c,0]; t1 precomputed into S_F0 ----
  do_radial(S_MLPA, false);
  {
    int half = t & 1, kh = half*8;
    const float* EB = sm + S_EB + el2*10;
    float g0 = EB[6], g1 = EB[7], g2 = EB[8];
    const float* f1 = sm + S_F1 + el2*48 + kh*3;
    float* t1 = sm + S_F0 + el2*16 + kh;
#pragma unroll
    for (int j = 0; j < 8; j++)
      t1[j] = f1[j*3]*g0 + f1[j*3+1]*g1 + f1[j*3+2]*g2;
  }
  w3store(wreg);
  __syncthreads();
#pragma unroll 1
  for (int eh = 0; eh < 2; eh++) {
    u64 acc[8][4];
    gemm8x8(sm + S_H2T + eh*64 + er*8, sm + S_W3 + cr*4, acc);
#pragma unroll
    for (int i = 0; i < 8; i++) {
      int el = eh*64 + er*8 + i;
      const u64* t1p = reinterpret_cast<const u64*>(sm + S_F0 + el*16 + khalf);
      u64 v2 = ffma2(acc[i][0], t1p[0], 0ull);
      v2 = ffma2(acc[i][1], t1p[1], v2);
      v2 = ffma2(acc[i][2], t1p[2], v2);
      v2 = ffma2(acc[i][3], t1p[3], v2);
      float2 q = unpk(v2);
      float v = q.x + q.y;
      v += __shfl_xor_sync(0xffffffffu, v, 1);
      if ((cr & 1) == 0) {
        int dd = reinterpret_cast<const int*>(sm + S_EB + el*10)[9];
        atomicAdd(p.out + (size_t)dd*64 + c*4, v);
      }
    }
  }
  stage_mlp(3, S_MLPB);
  w3load(g_W3T11, wreg);
  __syncthreads();

  // ---- chunks 3..5: pair11 (f = 0,1,2) -> o1 regs (no atomics) ----
  do_radial(S_MLPB, false);
  w3store(wreg);
  __syncthreads();
#pragma unroll 1
  for (int f = 0; f < 3; f++) {
#pragma unroll 1
    for (int eh = 0; eh < 2; eh++) {
      u64 acc[8][4];
      gemm8x8(sm + S_H2T + eh*64 + er*8, sm + S_W3 + cr*4, acc);
#pragma unroll
      for (int i = 0; i < 8; i++) {
        int el = eh*64 + er*8 + i;
        int idx = eh*8 + i;
        float rw[8]; unpack8(acc[i], rw);
        const float* f1 = sm + S_F1 + el*48 + khalf*3;
        float s0 = 0.f, s1 = 0.f, s2 = 0.f;
#pragma unroll
        for (int j = 0; j < 8; j++) {
          float r = rw[j];
          s0 = fmaf(r, f1[j*3],   s0);
          s1 = fmaf(r, f1[j*3+1], s1);
          s2 = fmaf(r, f1[j*3+2], s2);
        }
        const float* B = sm + S_B11 + el*27 + f*3;   // B[i*9 + f*3 + o]
        o1[idx][0] += s0*B[0] + s1*B[9]  + s2*B[18];
        o1[idx][1] += s0*B[1] + s1*B[10] + s2*B[19];
        o1[idx][2] += s0*B[2] + s1*B[11] + s2*B[20];
      }
    }
    if (f < 2) {
      w3load(g_W3T11 + (f+1)*8192, wreg);
      __syncthreads();
      w3store(wreg);
      __syncthreads();
    }
  }

  // ---- flush degree-1 output: one shfl-reduce + 3 atomics per edge ----
#pragma unroll 1
  for (int eh = 0; eh < 2; eh++) {
#pragma unroll
    for (int i = 0; i < 8; i++) {
      int el = eh*64 + er*8 + i;
      int idx = eh*8 + i;
      float p0 = o1[idx][0], p1 = o1[idx][1], p2 = o1[idx][2];
      p0 += __shfl_xor_sync(0xffffffffu, p0, 1);
      p1 += __shfl_xor_sync(0xffffffffu, p1, 1);
      p2 += __shfl_xor_sync(0xffffffffu, p2, 1);
      if ((cr & 1) == 0) {
        int dd = reinterpret_cast<const int*>(sm + S_EB + el*10)[9];
        float* outp = p.out + (size_t)dd*64 + c*4;
        atomicAdd(outp + 1, p0);
        atomicAdd(outp + 2, p1);
        atomicAdd(outp + 3, p2);
      }
    }
  }
}

// ---------- scalar tail (E % 128 edges; weights from gmem) ----------
__device__ void radial_g(const float* w1, const float* b1, const float* w2,
                         const float* b2, float ei0, float ei1, float h2[32]) {
  float h1[32];
  for (int m = 0; m < 32; m++)
    h1[m] = fmaxf(fmaf(ei0, w1[m], fmaf(ei1, w1[32+m], b1[m])), 0.f);
  for (int m = 0; m < 32; m++) {
    float a = b2[m];
    for (int n = 0; n < 32; n++) a = fmaf(h1[n], w2[n*32 + m], a);
    h2[m] = fmaxf(a, 0.f);
  }
}

__global__ void convTail(P p, int e0) {
  int e = e0 + threadIdx.x;
  if (e >= p.E) return;
  int s = p.src[e], d = p.dst[e];
  float ei0 = p.edge_inv[2*e], ei1 = p.edge_inv[2*e+1];
  float f0[16], f1[48];
  for (int i = 0; i < 16; i++) f0[i] = p.feat0[(size_t)s*16 + i];
  for (int i = 0; i < 48; i++) f1[i] = p.feat1[(size_t)s*48 + i];
  float h2[32], out0[16], o1[48];
  for (int c = 0; c < 16; c++) out0[c] = 0.f;
  for (int j = 0; j < 48; j++) o1[j] = 0.f;
  radial_g(p.w1[0], p.bb1[0], p.w2[0], p.bb2[0], ei0, ei1, h2);
  float bv = p.b00[e];
  for (int c = 0; c < 16; c++) {
    float v = 0.f;
    for (int k = 0; k < 16; k++) {
      float rw = 0.f;
      for (int m = 0; m < 32; m++) rw = fmaf(h2[m], p.w3[0][m*256 + c*16 + k], rw);
      v = fmaf(rw, f0[k], v);
    }
    out0[c] += v * bv;
  }
  radial_g(p.w1[1], p.bb1[1], p.w2[1], p.bb2[1], ei0, ei1, h2);
  float q0 = p.b01[e*3], q1 = p.b01[e*3+1], q2 = p.b01[e*3+2];
  for (int c = 0; c < 16; c++) {
    float v = 0.f;
    for (int k = 0; k < 16; k++) {
      float rw = 0.f;
      for (int m = 0; m < 32; m++) rw = fmaf(h2[m], p.w3[1][m*256 + c*16 + k], rw);
      v = fmaf(rw, f0[k], v);
    }
    o1[c*3] += v*q0; o1[c*3+1] += v*q1; o1[c*3+2] += v*q2;
  }
  radial_g(p.w1[2], p.bb1[2], p.w2[2], p.bb2[2], ei0, ei1, h2);
  float g0 = p.b10[e*3], g1 = p.b10[e*3+1], g2 = p.b10[e*3+2];
  for (int c = 0; c < 16; c++) {
    float v = 0.f;
    for (int k = 0; k < 16; k++) {
      float rw = 0.f;
      for (int m = 0; m < 32; m++) rw = fmaf(h2[m], p.w3[2][m*256 + c*16 + k], rw);
      v = fmaf(rw, f1[k*3]*g0 + f1[k*3+1]*g1 + f1[k*3+2]*g2, v);
    }
    out0[c] += v;
  }
  radial_g(p.w1[3], p.bb1[3], p.w2[3], p.bb2[3], ei0, ei1, h2);
  for (int c = 0; c < 16; c++) {
    for (int k = 0; k < 16; k++) {
      for (int f = 0; f < 3; f++) {
        float rw = 0.f;
        for (int m = 0; m < 32; m++) rw = fmaf(h2[m], p.w3[3][m*768 + c*48 + k*3 + f], rw);
        for (int o = 0; o < 3; o++) {
          float tt = f1[k*3]*p.b11[(size_t)e*27 + f*3 + o]
                   + f1[k*3+1]*p.b11[(size_t)e*27 + 9 + f*3 + o]
                   + f1[k*3+2]*p.b11[(size_t)e*27 + 18 + f*3 + o];
          o1[c*3+o] = fmaf(rw, tt, o1[c*3+o]);
        }
      }
    }
  }
  float* outp = p.out + (size_t)d * 64;
  for (int c = 0; c < 16; c++) {
    atomicAdd(outp + c*4,     out0[c]);
    atomicAdd(outp + c*4 + 1, o1[c*3]);
    atomicAdd(outp + c*4 + 2, o1[c*3+1]);
    atomicAdd(outp + c*4 + 3, o1[c*3+2]);
  }
}

}  // namespace

extern "C" void kernel_launch(void* const* d_in, const int* in_sizes, int n_in,
                              void* d_out, int out_size) {
  P p{};
  p.feat0    = (const float*)d_in[0];
  p.feat1    = (const float*)d_in[1];
  p.edge_inv = (const float*)d_in[2];
  p.src      = (const int*)d_in[3];
  p.dst      = (const int*)d_in[4];
  p.b00 = (const float*)d_in[5];
  p.b01 = (const float*)d_in[6];
  p.b10 = (const float*)d_in[7];
  p.b11 = (const float*)d_in[8];
  const int base[4] = {9, 14, 19, 24};   // 00, 01, 10, 11
  for (int pr = 0; pr < 4; pr++) {
    p.w1[pr]  = (const float*)d_in[base[pr]];
    p.bb1[pr] = (const float*)d_in[base[pr]+1];
    p.w2[pr]  = (const float*)d_in[base[pr]+2];
    p.bb2[pr] = (const float*)d_in[base[pr]+3];
    p.w3[pr]  = (const float*)d_in[base[pr]+4];
  }
  p.out = (float*)d_out;
  p.E = in_sizes[3];

  static bool attr_done = false;
  if (!attr_done) {
    cudaFuncSetAttribute(convFused, cudaFuncAttributeMaxDynamicSharedMemorySize,
                         S_TOT * 4);
    attr_done = true;
  }

  int nblk = (out_size + 255) / 256;
  if (nblk < 96) nblk = 96;
  prolog<<<nblk, 256>>>(p.w3[3], p.out, out_size);

  int nfull = p.E / 128;
  if (nfull > 0) convFused<<<nfull, 256, S_TOT * 4>>>(p);
  int tail = p.E - nfull * 128;
  if (tail > 0) convTail<<<1, tail>>>(p, nfull * 128);
}